// round 13
// baseline (speedup 1.0000x reference)
#include <cuda_runtime.h>
#include <cuda_bf16.h>
#include <stdint.h>
#include <math.h>

// Problem dims
#define BB 64
#define LL 512
#define EE 256
#define HH 8
#define NN 32
#define DC 4
#define DI 512
#define DTR 16
#define MROWS (BB*LL)   // 32768

#define WTOT 614400     // total packed weight pairs across all 8 matrices

// ---------------- scratch (static device globals; no allocs) ----------------
__device__ float g_seqs  [MROWS*EE];
__device__ float g_xz    [MROWS*(2*DI)];
__device__ float g_uconv [MROWS*DI];
__device__ float g_xdbl  [MROWS*80];
__device__ float g_dt    [MROWS*DI];
__device__ float g_ymam  [MROWS*DI];
__device__ float g_mamba [MROWS*EE];
__device__ float g_qkv   [MROWS*(3*EE)];
__device__ float g_ctx   [MROWS*EE];
__device__ float g_attno [MROWS*EE];
__device__ float g_comb  [MROWS*EE];
__device__ float g_ffh   [MROWS*(4*EE)];
__device__ float g_ff    [MROWS*EE];
__device__ float g_gate  [BB];
__device__ __align__(16) unsigned g_WH[WTOT];
__device__ __align__(16) unsigned g_WL[WTOT];

// ---------------- embedding + positional ----------------
__global__ void embed_kernel(const int* __restrict__ log_seqs,
                             const float* __restrict__ item_emb,
                             const float* __restrict__ pos_emb) {
    int i = blockIdx.x * blockDim.x + threadIdx.x;   // over MROWS*EE
    int row = i >> 8;           // b*L + l
    int e   = i & 255;
    int l   = row & (LL-1);
    int it  = __ldg(&log_seqs[row]);
    g_seqs[i] = item_emb[(size_t)it*EE + e] * 16.0f + pos_emb[l*EE + e];
}

// ---------------- BF16 split helpers ----------------
__device__ __forceinline__ void split_bf16x2(float a, float b, unsigned& hi, unsigned& lo) {
    __nv_bfloat162 h = __floats2bfloat162_rn(a, b);   // .x = a (low 16 bits)
    float ra = a - __bfloat162float(h.x);
    float rb = b - __bfloat162float(h.y);
    __nv_bfloat162 l = __floats2bfloat162_rn(ra, rb);
    hi = *reinterpret_cast<unsigned*>(&h);
    lo = *reinterpret_cast<unsigned*>(&l);
}
__device__ __forceinline__ void mma_bf16(float c[4], const unsigned a[4], const unsigned b[2]) {
    asm volatile(
        "mma.sync.aligned.m16n8k16.row.col.f32.bf16.bf16.f32 "
        "{%0,%1,%2,%3},{%4,%5,%6,%7},{%8,%9},{%0,%1,%2,%3};"
        : "+f"(c[0]), "+f"(c[1]), "+f"(c[2]), "+f"(c[3])
        : "r"(a[0]), "r"(a[1]), "r"(a[2]), "r"(a[3]), "r"(b[0]), "r"(b[1]));
}

// FMA-pipe exp (no MUFU): exp(x) for x <= 0, clamped below at -80.
__device__ __forceinline__ float fexp(float x) {
    float t = fmaxf(x, -80.f) * 1.4426950408889634f;
    float z = t + 12582912.f;
    int   i = __float_as_int(z) - 0x4B400000;
    float f = t - (z - 12582912.f);
    float p =      1.3333558146e-3f;
    p = fmaf(p, f, 9.6181291076e-3f);
    p = fmaf(p, f, 5.5504108664e-2f);
    p = fmaf(p, f, 2.4022650696e-1f);
    p = fmaf(p, f, 6.9314718056e-1f);
    p = fmaf(p, f, 1.0f);
    return __int_as_float(__float_as_int(p) + (i << 23));
}

// ---------------- weight pre-split: W[N][K] fp32 -> fragment-order bf16 hi/lo ----
// Layout per matrix: idx = base + ((n8b*(K/16) + kstep)*32 + sigma)*2 + khi
struct PSDesc {
    const float* W[8];
    int K[8];
    int cum[9];
};
__global__ void presplit_kernel(PSDesc ps) {
    int t = blockIdx.x * blockDim.x + threadIdx.x;   // global pair index
    if (t >= ps.cum[8]) return;
    int m = 0;
    #pragma unroll
    for (int i = 1; i < 8; i++) if (t >= ps.cum[i]) m = i;
    int p  = t - ps.cum[m];
    int K  = ps.K[m];
    int kh = K >> 1;
    int n  = p / kh;
    int kp = p - n*kh;
    int kstep = kp >> 3;
    int pp = kp & 7;
    int kq = pp & 3, khi = pp >> 2;
    int gid = n & 7, n8b = n >> 3;
    int sig = kq*8 + ((gid + 2*kq) & 7);
    int idx = ps.cum[m] + ((n8b*(K>>4) + kstep)*32 + sig)*2 + khi;
    const float* W = ps.W[m];
    int k = kp*2;
    unsigned hi, lo;
    split_bf16x2(W[(size_t)n*K + k], W[(size_t)n*K + k + 1], hi, lo);
    g_WH[idx] = hi;
    g_WL[idx] = lo;
}

// ---------------- tensor-core GEMM v3: 4 warps, warp tile 64x64 ----------------
// C = act(A[M,K](lda) * W[N,K]^T + bias); M%128==0, K%16==0, N%8==0.
// Block tile 128x128, 128 threads, double-buffered fragment-order smem,
// B loaded pre-split from g_WH/g_WL via LDG.128. LDS/MMA halved vs 8-warp version.
__global__ __launch_bounds__(128, 2)
void gemm_bf16_kernel(const float* __restrict__ A, int lda,
                      const unsigned* __restrict__ WH,
                      const unsigned* __restrict__ WL,
                      int nN8,
                      const float* __restrict__ bias,
                      float* __restrict__ C,
                      int M, int N, int K, int act) {
    __shared__ uint4 AH4[2][8][32];
    __shared__ uint4 AL4[2][8][32];
    __shared__ uint2 BH2[2][16][32];
    __shared__ uint2 BL2[2][16][32];

    int tid  = threadIdx.x;
    int lane = tid & 31;
    int wid  = tid >> 5;        // 0..3
    int wm = wid >> 1;          // 0..1 -> rows wm*64
    int wn = wid & 1;           // 0..1 -> cols wn*64
    int gid = lane >> 2;
    int kq  = lane & 3;
    int slot = kq*8 + ((gid + 2*kq) & 7);

    int m0 = blockIdx.y * 128;
    int n0 = blockIdx.x * 128;
    int nKt = K >> 4;

    // A producer coords: thread = row, full 16-k slice
    int lr = tid;               // 0..127
    int am16b = lr >> 4;
    int pgid  = lr & 7;
    int ahalf = (lr >> 3) & 1;
    int sA0 =      ((pgid    ) & 7);
    int sA1 = 8  + ((pgid + 2) & 7);
    int sA2 = 16 + ((pgid + 4) & 7);
    int sA3 = 24 + ((pgid + 6) & 7);

    // B producer coords: 2 uint4 per thread per array (covers sigs 2q4, 2q4+1)
    int g0 = tid*2, g1 = g0+1;
    int bn0 = g0 >> 4, q40 = g0 & 15;
    int bn1 = g1 >> 4, q41 = g1 & 15;
    int bW = n0 >> 3;
    bool v0 = (bW + bn0) < nN8;
    bool v1 = (bW + bn1) < nN8;
    const uint4* WH4 = (const uint4*)WH;
    const uint4* WL4 = (const uint4*)WL;
    size_t wb0 = ((size_t)(bW+bn0)*nKt)*16 + q40;   // uint4 units; +it*16 per iter
    size_t wb1 = ((size_t)(bW+bn1)*nKt)*16 + q41;

    float acc[4][8][4];
    #pragma unroll
    for (int i=0;i<4;i++)
        #pragma unroll
        for (int j=0;j<8;j++)
            #pragma unroll
            for (int r=0;r<4;r++) acc[i][j][r]=0.f;

    const float* aptr = A + (size_t)(m0+lr)*lda;

    // prologue: stage 0
    float4 a0 = *(const float4*)(aptr + 0);
    float4 a1 = *(const float4*)(aptr + 4);
    float4 a2 = *(const float4*)(aptr + 8);
    float4 a3 = *(const float4*)(aptr + 12);
    uint4 bh0 = v0 ? WH4[wb0] : make_uint4(0u,0u,0u,0u);
    uint4 bh1 = v1 ? WH4[wb1] : make_uint4(0u,0u,0u,0u);
    uint4 bl0 = v0 ? WL4[wb0] : make_uint4(0u,0u,0u,0u);
    uint4 bl1 = v1 ? WL4[wb1] : make_uint4(0u,0u,0u,0u);
    {
        unsigned h, l;
        split_bf16x2(a0.x, a0.y, h, l);
        ((unsigned*)&AH4[0][am16b][sA0])[ahalf]=h;   ((unsigned*)&AL4[0][am16b][sA0])[ahalf]=l;
        split_bf16x2(a0.z, a0.w, h, l);
        ((unsigned*)&AH4[0][am16b][sA1])[ahalf]=h;   ((unsigned*)&AL4[0][am16b][sA1])[ahalf]=l;
        split_bf16x2(a1.x, a1.y, h, l);
        ((unsigned*)&AH4[0][am16b][sA2])[ahalf]=h;   ((unsigned*)&AL4[0][am16b][sA2])[ahalf]=l;
        split_bf16x2(a1.z, a1.w, h, l);
        ((unsigned*)&AH4[0][am16b][sA3])[ahalf]=h;   ((unsigned*)&AL4[0][am16b][sA3])[ahalf]=l;
        split_bf16x2(a2.x, a2.y, h, l);
        ((unsigned*)&AH4[0][am16b][sA0])[ahalf+2]=h; ((unsigned*)&AL4[0][am16b][sA0])[ahalf+2]=l;
        split_bf16x2(a2.z, a2.w, h, l);
        ((unsigned*)&AH4[0][am16b][sA1])[ahalf+2]=h; ((unsigned*)&AL4[0][am16b][sA1])[ahalf+2]=l;
        split_bf16x2(a3.x, a3.y, h, l);
        ((unsigned*)&AH4[0][am16b][sA2])[ahalf+2]=h; ((unsigned*)&AL4[0][am16b][sA2])[ahalf+2]=l;
        split_bf16x2(a3.z, a3.w, h, l);
        ((unsigned*)&AH4[0][am16b][sA3])[ahalf+2]=h; ((unsigned*)&AL4[0][am16b][sA3])[ahalf+2]=l;
        ((uint4*)&BH2[0][bn0][0])[q40] = bh0;
        ((uint4*)&BH2[0][bn1][0])[q41] = bh1;
        ((uint4*)&BL2[0][bn0][0])[q40] = bl0;
        ((uint4*)&BL2[0][bn1][0])[q41] = bl1;
    }
    __syncthreads();

    int nIter = K >> 4;
    for (int it = 0; it < nIter; it++) {
        int s = it & 1;
        bool more = (it + 1) < nIter;

        // prefetch next tiles (latency hidden under 96 MMAs below)
        if (more) {
            int ko = (it+1) << 4;
            a0 = *(const float4*)(aptr + ko + 0);
            a1 = *(const float4*)(aptr + ko + 4);
            a2 = *(const float4*)(aptr + ko + 8);
            a3 = *(const float4*)(aptr + ko + 12);
            size_t o = (size_t)(it+1)*16;
            bh0 = v0 ? WH4[wb0 + o] : make_uint4(0u,0u,0u,0u);
            bh1 = v1 ? WH4[wb1 + o] : make_uint4(0u,0u,0u,0u);
            bl0 = v0 ? WL4[wb0 + o] : make_uint4(0u,0u,0u,0u);
            bl1 = v1 ? WL4[wb1 + o] : make_uint4(0u,0u,0u,0u);
        }

        // A-hi fragments (4 x LDS.128, conflict-free)
        unsigned fah[4][4];
        #pragma unroll
        for (int mi=0; mi<4; mi++) {
            uint4 v = AH4[s][wm*4+mi][slot];
            fah[mi][0]=v.x; fah[mi][1]=v.y; fah[mi][2]=v.z; fah[mi][3]=v.w;
        }
        // B-hi fragments (8 x LDS.64, conflict-free)
        unsigned fb[8][2];
        #pragma unroll
        for (int ni=0; ni<8; ni++) {
            uint2 v = BH2[s][wn*8+ni][slot];
            fb[ni][0]=v.x; fb[ni][1]=v.y;
        }
        // pass 1: Ahi*Bhi
        #pragma unroll
        for (int mi=0; mi<4; mi++)
            #pragma unroll
            for (int ni=0; ni<8; ni++)
                mma_bf16(acc[mi][ni], fah[mi], fb[ni]);
        // pass 2: Alo*Bhi
        {
            unsigned fal[4][4];
            #pragma unroll
            for (int mi=0; mi<4; mi++) {
                uint4 v = AL4[s][wm*4+mi][slot];
                fal[mi][0]=v.x; fal[mi][1]=v.y; fal[mi][2]=v.z; fal[mi][3]=v.w;
            }
            #pragma unroll
            for (int mi=0; mi<4; mi++)
                #pragma unroll
                for (int ni=0; ni<8; ni++)
                    mma_bf16(acc[mi][ni], fal[mi], fb[ni]);
        }
        // pass 3: Ahi*Blo
        #pragma unroll
        for (int ni=0; ni<8; ni++) {
            uint2 v = BL2[s][wn*8+ni][slot];
            fb[ni][0]=v.x; fb[ni][1]=v.y;
        }
        #pragma unroll
        for (int mi=0; mi<4; mi++)
            #pragma unroll
            for (int ni=0; ni<8; ni++)
                mma_bf16(acc[mi][ni], fah[mi], fb[ni]);

        // store next tiles into stage s^1 (overlaps MMA pipeline drain)
        if (more) {
            int d = s ^ 1;
            unsigned h, l;
            split_bf16x2(a0.x, a0.y, h, l);
            ((unsigned*)&AH4[d][am16b][sA0])[ahalf]=h;   ((unsigned*)&AL4[d][am16b][sA0])[ahalf]=l;
            split_bf16x2(a0.z, a0.w, h, l);
            ((unsigned*)&AH4[d][am16b][sA1])[ahalf]=h;   ((unsigned*)&AL4[d][am16b][sA1])[ahalf]=l;
            split_bf16x2(a1.x, a1.y, h, l);
            ((unsigned*)&AH4[d][am16b][sA2])[ahalf]=h;   ((unsigned*)&AL4[d][am16b][sA2])[ahalf]=l;
            split_bf16x2(a1.z, a1.w, h, l);
            ((unsigned*)&AH4[d][am16b][sA3])[ahalf]=h;   ((unsigned*)&AL4[d][am16b][sA3])[ahalf]=l;
            split_bf16x2(a2.x, a2.y, h, l);
            ((unsigned*)&AH4[d][am16b][sA0])[ahalf+2]=h; ((unsigned*)&AL4[d][am16b][sA0])[ahalf+2]=l;
            split_bf16x2(a2.z, a2.w, h, l);
            ((unsigned*)&AH4[d][am16b][sA1])[ahalf+2]=h; ((unsigned*)&AL4[d][am16b][sA1])[ahalf+2]=l;
            split_bf16x2(a3.x, a3.y, h, l);
            ((unsigned*)&AH4[d][am16b][sA2])[ahalf+2]=h; ((unsigned*)&AL4[d][am16b][sA2])[ahalf+2]=l;
            split_bf16x2(a3.z, a3.w, h, l);
            ((unsigned*)&AH4[d][am16b][sA3])[ahalf+2]=h; ((unsigned*)&AL4[d][am16b][sA3])[ahalf+2]=l;
            ((uint4*)&BH2[d][bn0][0])[q40] = bh0;
            ((uint4*)&BH2[d][bn1][0])[q41] = bh1;
            ((uint4*)&BL2[d][bn0][0])[q40] = bl0;
            ((uint4*)&BL2[d][bn1][0])[q41] = bl1;
        }
        __syncthreads();
    }

    // epilogue: per warp 4x8 m16n8 tiles
    #pragma unroll
    for (int mi=0; mi<4; mi++) {
        int r = m0 + wm*64 + mi*16 + gid;
        #pragma unroll
        for (int ni=0; ni<8; ni++) {
            int c = n0 + wn*64 + ni*8 + kq*2;
            if (c < N) {
                float v0e = acc[mi][ni][0], v1e = acc[mi][ni][1];
                float v2e = acc[mi][ni][2], v3e = acc[mi][ni][3];
                if (bias) {
                    float b0 = bias[c], b1 = bias[c+1];
                    v0e += b0; v1e += b1; v2e += b0; v3e += b1;
                }
                if (act == 1) {
                    v0e=fmaxf(v0e,0.f); v1e=fmaxf(v1e,0.f); v2e=fmaxf(v2e,0.f); v3e=fmaxf(v3e,0.f);
                } else if (act == 2) {
                    v0e = (v0e>20.f)?v0e:log1pf(__expf(v0e));
                    v1e = (v1e>20.f)?v1e:log1pf(__expf(v1e));
                    v2e = (v2e>20.f)?v2e:log1pf(__expf(v2e));
                    v3e = (v3e>20.f)?v3e:log1pf(__expf(v3e));
                }
                *(float2*)(C + (size_t)r*N + c)       = make_float2(v0e, v1e);
                *(float2*)(C + (size_t)(r+8)*N + c)   = make_float2(v2e, v3e);
            }
        }
    }
}

// ---------------- causal depthwise conv (DC=4) + SiLU ----------------
__global__ void conv_silu_kernel(const float* __restrict__ conv_w,
                                 const float* __restrict__ conv_b) {
    int i = blockIdx.x * blockDim.x + threadIdx.x;
    int row = i >> 9;
    int d   = i & (DI-1);
    int b   = row >> 9;
    int l   = row & (LL-1);
    float acc = conv_b[d];
    #pragma unroll
    for (int k=0;k<DC;k++) {
        int ll = l - (DC-1) + k;
        if (ll >= 0)
            acc = fmaf(g_xz[(size_t)((b<<9)+ll)*(2*DI) + d], conv_w[d*DC + k], acc);
    }
    float s = acc / (1.f + __expf(-acc));
    g_uconv[i] = s;
}

// ---------------- selective scan v2 ----------------
#define TCH 16
__global__ __launch_bounds__(128)
void scan2_kernel(const float* __restrict__ A_log,
                  const float* __restrict__ Dp) {
    __shared__ float sBC[TCH][64];
    int b = blockIdx.x >> 2;
    int q = blockIdx.x & 3;
    int d = q*128 + threadIdx.x;
    int brow = b << 9;

    float h[32];
    #pragma unroll
    for (int n=0;n<32;n++) h[n]=0.f;
    float dpv = Dp[d];

    bool fast = true;
    #pragma unroll
    for (int n=0;n<32;n++) {
        float a = -__expf(A_log[d*NN + n]);
        if (fabsf(a + (float)(n+1)) > 1e-3f*(float)(n+1)) fast = false;
    }

    for (int t0=0; t0<LL; t0+=TCH) {
        __syncthreads();
        #pragma unroll
        for (int it=0; it<2; it++) {
            int p  = it*128 + threadIdx.x;
            int t  = p >> 4;
            int j  = (p & 15) * 4;
            *(float4*)&sBC[t][j] =
                *(const float4*)&g_xdbl[(size_t)(brow+t0+t)*80 + DTR + j];
        }
        __syncthreads();

        if (fast) {
            #pragma unroll 4
            for (int tt=0; tt<TCH; tt++) {
                int row = brow + t0 + tt;
                float dtv = g_dt   [(size_t)row*DI + d];
                float uv  = g_uconv[(size_t)row*DI + d];
                float p  = __expf(-dtv);
                float du = dtv * uv;
                float w  = 1.f;
                float y0=0.f,y1=0.f,y2=0.f,y3=0.f;
                #pragma unroll
                for (int n=0;n<32;n+=4) {
                    w *= p; h[n  ]=fmaf(w,h[n  ],du*sBC[tt][n  ]); y0=fmaf(h[n  ],sBC[tt][32+n  ],y0);
                    w *= p; h[n+1]=fmaf(w,h[n+1],du*sBC[tt][n+1]); y1=fmaf(h[n+1],sBC[tt][33+n  ],y1);
                    w *= p; h[n+2]=fmaf(w,h[n+2],du*sBC[tt][n+2]); y2=fmaf(h[n+2],sBC[tt][34+n  ],y2);
                    w *= p; h[n+3]=fmaf(w,h[n+3],du*sBC[tt][n+3]); y3=fmaf(h[n+3],sBC[tt][35+n  ],y3);
                }
                float y = (y0+y1)+(y2+y3);
                float z  = g_xz[(size_t)row*(2*DI) + DI + d];
                float sz = z / (1.f + __expf(-z));
                g_ymam[(size_t)row*DI + d] = (y + uv*dpv) * sz;
            }
        } else {
            for (int tt=0; tt<TCH; tt++) {
                int row = brow + t0 + tt;
                float dtv = g_dt   [(size_t)row*DI + d];
                float uv  = g_uconv[(size_t)row*DI + d];
                float du = dtv * uv;
                float y = 0.f;
                #pragma unroll
                for (int n=0;n<32;n++) {
                    float a = -__expf(A_log[d*NN + n]);
                    float e = __expf(dtv * a);
                    h[n] = fmaf(e, h[n], du*sBC[tt][n]);
                    y = fmaf(h[n], sBC[tt][32+n], y);
                }
                float z  = g_xz[(size_t)row*(2*DI) + DI + d];
                float sz = z / (1.f + __expf(-z));
                g_ymam[(size_t)row*DI + d] = (y + uv*dpv) * sz;
            }
        }
    }
}

// ---------------- attention: FA2-style bf16 mma ----------------
__global__ __launch_bounds__(256)
void attn_mma_kernel() {
    __shared__ uint2 KH[2][4][32], KL[2][4][32];
    __shared__ uint2 VH[2][4][32], VL[2][4][32];

    int bh = blockIdx.x >> 1;
    int qh = blockIdx.x & 1;
    int b  = bh >> 3, h = bh & 7;
    int brow = b << 9;
    int tid = threadIdx.x;
    int w = tid >> 5, lane = tid & 31;
    int gid = lane >> 2, kq = lane & 3;
    int slot = kq*8 + ((gid + 2*kq) & 7);
    const float scale = 0.17677669529663687f;

    int qb = qh*256 + w*32;
    unsigned qa_h[2][2][4], qa_l[2][2][4];
    #pragma unroll
    for (int mi=0; mi<2; mi++) {
        int r0 = brow + qb + mi*16 + gid;
        const float* q0 = g_qkv + (size_t)r0*(3*EE) + h*32;
        const float* q1 = q0 + (size_t)8*(3*EE);
        #pragma unroll
        for (int ks=0; ks<2; ks++) {
            int dA = 16*ks + 2*kq;
            float2 v0 = *(const float2*)(q0 + dA);
            float2 v1 = *(const float2*)(q1 + dA);
            float2 v2 = *(const float2*)(q0 + dA + 8);
            float2 v3 = *(const float2*)(q1 + dA + 8);
            split_bf16x2(v0.x*scale, v0.y*scale, qa_h[mi][ks][0], qa_l[mi][ks][0]);
            split_bf16x2(v1.x*scale, v1.y*scale, qa_h[mi][ks][1], qa_l[mi][ks][1]);
            split_bf16x2(v2.x*scale, v2.y*scale, qa_h[mi][ks][2], qa_l[mi][ks][2]);
            split_bf16x2(v3.x*scale, v3.y*scale, qa_h[mi][ks][3], qa_l[mi][ks][3]);
        }
    }

    float o[2][4][4];
    #pragma unroll
    for (int mi=0;mi<2;mi++)
        #pragma unroll
        for (int vb=0;vb<4;vb++)
            #pragma unroll
            for (int c=0;c<4;c++) o[mi][vb][c]=0.f;
    float mrun[2][2] = {{-1e30f,-1e30f},{-1e30f,-1e30f}};
    float lrun[2][2] = {{0.f,0.f},{0.f,0.f}};

    int pkn  = tid >> 3;
    int pkd0 = (tid & 7) * 4;
    int pkks = pkd0 >> 4;
    int pkp0 = (pkd0 & 15) >> 1;
    int pkkq0 = pkp0 & 3, pkkhi = pkp0 >> 2;
    int pkbn = pkn >> 3, pkg = pkn & 7;
    int pksA = pkkq0*8 + ((pkg + 2*pkkq0) & 7);
    int pksB = (pkkq0+1)*8 + ((pkg + 2*(pkkq0+1)) & 7);
    int pvp  = tid >> 4;
    int pvd0 = (tid & 15) * 2;
    int pvks = pvp >> 3;
    int pvq  = (pvp & 7) & 3, pvkhi = (pvp & 7) >> 2;
    int pvbnA = pvd0 >> 3,      pvsA = pvq*8 + (((pvd0 & 7) + 2*pvq) & 7);
    int pvbnB = (pvd0+1) >> 3,  pvsB = pvq*8 + ((((pvd0+1) & 7) + 2*pvq) & 7);

    for (int kt = 0; kt < 16; kt++) {
        __syncthreads();
        {
            const float* kp = g_qkv + (size_t)(brow + kt*32 + pkn)*(3*EE) + EE + h*32 + pkd0;
            float4 kv = *(const float4*)kp;
            unsigned hi, lo;
            split_bf16x2(kv.x, kv.y, hi, lo);
            ((unsigned*)&KH[pkks][pkbn][pksA])[pkkhi]=hi; ((unsigned*)&KL[pkks][pkbn][pksA])[pkkhi]=lo;
            split_bf16x2(kv.z, kv.w, hi, lo);
            ((unsigned*)&KH[pkks][pkbn][pksB])[pkkhi]=hi; ((unsigned*)&KL[pkks][pkbn][pksB])[pkkhi]=lo;
        }
        {
            const float* v0p = g_qkv + (size_t)(brow + kt*32 + 2*pvp)*(3*EE) + 2*EE + h*32 + pvd0;
            const float* v1p = v0p + 3*EE;
            float2 va = *(const float2*)v0p;
            float2 vb = *(const float2*)v1p;
            unsigned hi, lo;
            split_bf16x2(va.x, vb.x, hi, lo);
            ((unsigned*)&VH[pvks][pvbnA][pvsA])[pvkhi]=hi; ((unsigned*)&VL[pvks][pvbnA][pvsA])[pvkhi]=lo;
            split_bf16x2(va.y, vb.y, hi, lo);
            ((unsigned*)&VH[pvks][pvbnB][pvsB])[pvkhi]=hi; ((unsigned*)&VL[pvks][pvbnB][pvsB])[pvkhi]=lo;
        }
        __syncthreads();

        float sa[2][4][4];
        #pragma unroll
        for (int mi=0;mi<2;mi++)
            #pragma unroll
            for (int bn=0;bn<4;bn++)
                #pragma unroll
                for (int c=0;c<4;c++) sa[mi][bn][c]=0.f;
        #pragma unroll
        for (int bn=0; bn<4; bn++) {
            #pragma unroll
            for (int ks=0; ks<2; ks++) {
                uint2 kh2 = KH[ks][bn][slot];
                unsigned kh[2] = {kh2.x, kh2.y};
                uint2 kl2 = KL[ks][bn][slot];
                unsigned kl[2] = {kl2.x, kl2.y};
                #pragma unroll
                for (int mi=0; mi<2; mi++) {
                    mma_bf16(sa[mi][bn], qa_h[mi][ks], kh);
                    mma_bf16(sa[mi][bn], qa_l[mi][ks], kh);
                    mma_bf16(sa[mi][bn], qa_h[mi][ks], kl);
                }
            }
        }

        #pragma unroll
        for (int mi=0; mi<2; mi++) {
            #pragma unroll
            for (int rr=0; rr<2; rr++) {
                int c0 = rr*2;
                float mx = -1e30f;
                #pragma unroll
                for (int bn=0; bn<4; bn++) {
                    mx = fmaxf(mx, sa[mi][bn][c0]);
                    mx = fmaxf(mx, sa[mi][bn][c0+1]);
                }
                mx = fmaxf(mx, __shfl_xor_sync(0xffffffffu, mx, 1));
                mx = fmaxf(mx, __shfl_xor_sync(0xffffffffu, mx, 2));
                float mnew = fmaxf(mrun[mi][rr], mx);
                float corr = fexp(mrun[mi][rr] - mnew);
                mrun[mi][rr] = mnew;
                float psum = 0.f;
                #pragma unroll
                for (int bn=0; bn<4; bn++) {
                    float p0 = fexp(sa[mi][bn][c0]   - mnew);
                    float p1 = fexp(sa[mi][bn][c0+1] - mnew);
                    sa[mi][bn][c0]   = p0;
                    sa[mi][bn][c0+1] = p1;
                    psum += p0 + p1;
                }
                psum += __shfl_xor_sync(0xffffffffu, psum, 1);
                psum += __shfl_xor_sync(0xffffffffu, psum, 2);
                lrun[mi][rr] = lrun[mi][rr]*corr + psum;
                #pragma unroll
                for (int vb=0; vb<4; vb++) {
                    o[mi][vb][c0]   *= corr;
                    o[mi][vb][c0+1] *= corr;
                }
            }
        }

        #pragma unroll
        for (int mi=0; mi<2; mi++) {
            #pragma unroll
            for (int j=0; j<2; j++) {
                unsigned pa_h[4], pa_l[4];
                split_bf16x2(sa[mi][2*j  ][0], sa[mi][2*j  ][1], pa_h[0], pa_l[0]);
                split_bf16x2(sa[mi][2*j  ][2], sa[mi][2*j  ][3], pa_h[1], pa_l[1]);
                split_bf16x2(sa[mi][2*j+1][0], sa[mi][2*j+1][1], pa_h[2], pa_l[2]);
                split_bf16x2(sa[mi][2*j+1][2], sa[mi][2*j+1][3], pa_h[3], pa_l[3]);
                #pragma unroll
                for (int vb=0; vb<4; vb++) {
                    uint2 vh2 = VH[j][vb][slot];
                    unsigned vh[2] = {vh2.x, vh2.y};
                    mma_bf16(o[mi][vb], pa_h, vh);
                    mma_bf16(o[mi][vb], pa_l, vh);
                    uint2 vl2 = VL[j][vb][slot];
                    unsigned vl[2] = {vl2.x, vl2.y};
                    mma_bf16(o[mi][vb], pa_h, vl);
                }
            }
        }
    }

    #pragma unroll
    for (int mi=0; mi<2; mi++) {
        float inv0 = 1.f / lrun[mi][0];
        float inv1 = 1.f / lrun[mi][1];
        int r0 = brow + qb + mi*16 + gid;
        float* c0p = g_ctx + (size_t)r0*EE + h*32;
        float* c1p = c0p + (size_t)8*EE;
        #pragma unroll
        for (int vb=0; vb<4; vb++) {
            int cc = vb*8 + kq*2;
            *(float2*)(c0p + cc) = make_float2(o[mi][vb][0]*inv0, o[mi][vb][1]*inv0);
            *(float2*)(c1p + cc) = make_float2(o[mi][vb][2]*inv1, o[mi][vb][3]*inv1);
        }
    }
}

// ---------------- fused: add + LayerNorm(ln1) + gated combine -> g_comb ----------------
__global__ void add_ln_combine_kernel(const float* __restrict__ x, const float* __restrict__ res,
                                      const float* __restrict__ g, const float* __restrict__ bta) {
    int row  = blockIdx.x * (blockDim.x >> 5) + (threadIdx.x >> 5);
    int lane = threadIdx.x & 31;
    const float4* xp = (const float4*)(x   + (size_t)row*EE);
    const float4* rp = (const float4*)(res + (size_t)row*EE);
    float v[8];
    float4 a0 = xp[lane],     b0 = rp[lane];
    float4 a1 = xp[lane+32],  b1 = rp[lane+32];
    v[0]=a0.x+b0.x; v[1]=a0.y+b0.y; v[2]=a0.z+b0.z; v[3]=a0.w+b0.w;
    v[4]=a1.x+b1.x; v[5]=a1.y+b1.y; v[6]=a1.z+b1.z; v[7]=a1.w+b1.w;
    float s=0.f, s2=0.f;
    #pragma unroll
    for (int i=0;i<8;i++){ s += v[i]; s2 = fmaf(v[i], v[i], s2); }
    #pragma unroll
    for (int off=16; off; off>>=1) {
        s  += __shfl_xor_sync(0xffffffffu, s,  off);
        s2 += __shfl_xor_sync(0xffffffffu, s2, off);
    }
    float mean = s * (1.f/EE);
    float var  = s2 * (1.f/EE) - mean*mean;
    float rstd = rsqrtf(var + 1e-6f);
    const float4* gp = (const float4*)g;
    const float4* bp = (const float4*)bta;
    float4 g0=gp[lane], g1=gp[lane+32], c0=bp[lane], c1=bp[lane+32];
    const float4* mp = (const float4*)(g_mamba + (size_t)row*EE);
    float4 m0 = mp[lane], m1 = mp[lane+32];
    float w = g_gate[row >> 9];
    float iw = 1.f - w;
    float4* op = (float4*)(g_comb + (size_t)row*EE);
    float4 o0, o1;
    o0.x = w*m0.x + iw*((v[0]-mean)*rstd*g0.x+c0.x);
    o0.y = w*m0.y + iw*((v[1]-mean)*rstd*g0.y+c0.y);
    o0.z = w*m0.z + iw*((v[2]-mean)*rstd*g0.z+c0.z);
    o0.w = w*m0.w + iw*((v[3]-mean)*rstd*g0.w+c0.w);
    o1.x = w*m1.x + iw*((v[4]-mean)*rstd*g1.x+c1.x);
    o1.y = w*m1.y + iw*((v[5]-mean)*rstd*g1.y+c1.y);
    o1.z = w*m1.z + iw*((v[6]-mean)*rstd*g1.z+c1.z);
    o1.w = w*m1.w + iw*((v[7]-mean)*rstd*g1.w+c1.w);
    op[lane]    = o0;
    op[lane+32] = o1;
}

// ---------------- fused: add + LayerNorm(ln2) + pos/neg logits -> out ----------------
__global__ void add_ln_logits_kernel(const float* __restrict__ x, const float* __restrict__ res,
                                     const float* __restrict__ g, const float* __restrict__ bta,
                                     const int* __restrict__ pos, const int* __restrict__ neg,
                                     const float* __restrict__ item_emb, float* __restrict__ out) {
    int row  = blockIdx.x * (blockDim.x >> 5) + (threadIdx.x >> 5);
    int lane = threadIdx.x & 31;
    const float4* xp = (const float4*)(x   + (size_t)row*EE);
    const float4* rp = (const float4*)(res + (size_t)row*EE);
    float v[8];
    float4 a0 = xp[lane],     b0 = rp[lane];
    float4 a1 = xp[lane+32],  b1 = rp[lane+32];
    v[0]=a0.x+b0.x; v[1]=a0.y+b0.y; v[2]=a0.z+b0.z; v[3]=a0.w+b0.w;
    v[4]=a1.x+b1.x; v[5]=a1.y+b1.y; v[6]=a1.z+b1.z; v[7]=a1.w+b1.w;
    float s=0.f, s2=0.f;
    #pragma unroll
    for (int i=0;i<8;i++){ s += v[i]; s2 = fmaf(v[i], v[i], s2); }
    #pragma unroll
    for (int off=16; off; off>>=1) {
        s  += __shfl_xor_sync(0xffffffffu, s,  off);
        s2 += __shfl_xor_sync(0xffffffffu, s2, off);
    }
    float mean = s * (1.f/EE);
    float var  = s2 * (1.f/EE) - mean*mean;
    float rstd = rsqrtf(var + 1e-6f);
    const float4* gp = (const float4*)g;
    const float4* bp = (const float4*)bta;
    float4 g0=gp[lane], g1=gp[lane+32], c0=bp[lane], c1=bp[lane+32];
    float f[8];
    f[0]=(v[0]-mean)*rstd*g0.x+c0.x; f[1]=(v[1]-mean)*rstd*g0.y+c0.y;
    f[2]=(v[2]-mean)*rstd*g0.z+c0.z; f[3]=(v[3]-mean)*rstd*g0.w+c0.w;
    f[4]=(v[4]-mean)*rstd*g1.x+c1.x; f[5]=(v[5]-mean)*rstd*g1.y+c1.y;
    f[6]=(v[6]-mean)*rstd*g1.z+c1.z; f[7]=(v[7]-mean)*rstd*g1.w+c1.w;
    int pi = __ldg(&pos[row]), ni = __ldg(&neg[row]);
    const float4* pe = (const float4*)(item_emb + (size_t)pi*EE);
    const float4* ne = (const float4*)(item_emb + (size_t)ni*EE);
    float4 p0 = pe[lane], p1 = pe[lane+32];
    float4 n0 = ne[lane], n1 = ne[lane+32];
    float dp = f[0]*p0.x+f[1]*p0.y+f[2]*p0.z+f[3]*p0.w
             + f[4]*p1.x+f[5]*p1.y+f[6]*p1.z+f[7]*p1.w;
    float dn = f[0]*n0.x+f[1]*n0.y+f[2]*n0.z+f[3]*n0.w
             + f[4]*n1.x+f[5]*n1.y+f[6]*n1.z+f[7]*n1.w;
    #pragma unroll
    for (int off=16; off; off>>=1) {
        dp += __shfl_xor_sync(0xffffffffu, dp, off);
        dn += __shfl_xor_sync(0xffffffffu, dn, off);
    }
    if (lane == 0) {
        out[row]         = dp;
        out[MROWS + row] = dn;
    }
}

// ---------------- gate ----------------
__global__ void gate_kernel(const float* __restrict__ mw_w, const float* __restrict__ mw_b) {
    int b = blockIdx.x;
    int e = threadIdx.x;
    float s = 0.f;
    for (int l=0;l<LL;l++) s += g_seqs[(size_t)((b<<9)+l)*EE + e];
    s = (s * (1.f/LL)) * mw_w[e];
    __shared__ float red[256];
    red[e] = s; __syncthreads();
    for (int st=128; st; st>>=1) { if (e < st) red[e] += red[e+st]; __syncthreads(); }
    if (e == 0) g_gate[b] = 1.f / (1.f + __expf(-(red[0] + mw_b[0])));
}

// ---------------- host ----------------
static float* symaddr(const void* sym) {
    void* p = nullptr;
    cudaGetSymbolAddress(&p, sym);
    return (float*)p;
}

// matrix order: in_proj, x_proj, dt_proj, out_proj, attn_in, attn_out, ff1, ff2
static const int WBASE[9] = {0, 131072, 151552, 155648, 221184, 319488, 352256, 483328, 614400};

static void gemm(const float* A, int lda, const unsigned* WH, const unsigned* WL,
                 const float* bias, float* C, int M, int N, int K, int act) {
    dim3 grid((N + 127) / 128, M / 128);
    gemm_bf16_kernel<<<grid, 128>>>(A, lda, WH, WL, N >> 3, bias, C, M, N, K, act);
}

extern "C" void kernel_launch(void* const* d_in, const int* in_sizes, int n_in,
                              void* d_out, int out_size) {
    const int*   log_seqs  = (const int*)  d_in[1];
    const int*   pos_seqs  = (const int*)  d_in[2];
    const int*   neg_seqs  = (const int*)  d_in[3];
    const float* item_emb  = (const float*)d_in[4];
    const float* pos_emb   = (const float*)d_in[5];
    const float* in_proj_w = (const float*)d_in[6];
    const float* conv_w    = (const float*)d_in[7];
    const float* conv_b    = (const float*)d_in[8];
    const float* x_proj_w  = (const float*)d_in[9];
    const float* dt_proj_w = (const float*)d_in[10];
    const float* dt_proj_b = (const float*)d_in[11];
    const float* A_log     = (const float*)d_in[12];
    const float* Dp        = (const float*)d_in[13];
    const float* out_proj_w= (const float*)d_in[14];
    const float* attn_in_w = (const float*)d_in[15];
    const float* attn_in_b = (const float*)d_in[16];
    const float* attn_out_w= (const float*)d_in[17];
    const float* attn_out_b= (const float*)d_in[18];
    const float* ln1_g     = (const float*)d_in[19];
    const float* ln1_b     = (const float*)d_in[20];
    const float* mw_w      = (const float*)d_in[21];
    const float* mw_b      = (const float*)d_in[22];
    const float* ff_w1     = (const float*)d_in[23];
    const float* ff_b1     = (const float*)d_in[24];
    const float* ff_w2     = (const float*)d_in[25];
    const float* ff_b2     = (const float*)d_in[26];
    const float* ln2_g     = (const float*)d_in[27];
    const float* ln2_b     = (const float*)d_in[28];
    float* out = (float*)d_out;

    float* p_seqs   = symaddr(g_seqs);
    float* p_xz     = symaddr(g_xz);
    float* p_uconv  = symaddr(g_uconv);
    float* p_xdbl   = symaddr(g_xdbl);
    float* p_dt     = symaddr(g_dt);
    float* p_ymam   = symaddr(g_ymam);
    float* p_mamba  = symaddr(g_mamba);
    float* p_qkv    = symaddr(g_qkv);
    float* p_ctx    = symaddr(g_ctx);
    float* p_attno  = symaddr(g_attno);
    float* p_comb   = symaddr(g_comb);
    float* p_ffh    = symaddr(g_ffh);
    float* p_ff     = symaddr(g_ff);
    unsigned* p_WH  = (unsigned*)symaddr(g_WH);
    unsigned* p_WL  = (unsigned*)symaddr(g_WL);

    // 0. pre-split all weights into fragment-order bf16 hi/lo
    PSDesc ps;
    ps.W[0]=in_proj_w;  ps.K[0]=256;
    ps.W[1]=x_proj_w;   ps.K[1]=512;
    ps.W[2]=dt_proj_w;  ps.K[2]=16;
    ps.W[3]=out_proj_w; ps.K[3]=512;
    ps.W[4]=attn_in_w;  ps.K[4]=256;
    ps.W[5]=attn_out_w; ps.K[5]=256;
    ps.W[6]=ff_w1;      ps.K[6]=256;
    ps.W[7]=ff_w2;      ps.K[7]=1024;
    for (int i=0;i<9;i++) ps.cum[i] = WBASE[i];
    presplit_kernel<<<(WTOT + 255)/256, 256>>>(ps);

    // 1. embedding + positional; gate (depends only on seqs)
    embed_kernel<<<(MROWS*EE)/256, 256>>>(log_seqs, item_emb, pos_emb);
    gate_kernel<<<BB, 256>>>(mw_w, mw_b);

    // 2. Mamba branch
    gemm(p_seqs, EE, p_WH+WBASE[0], p_WL+WBASE[0], nullptr, p_xz, MROWS, 2*DI, EE, 0);
    conv_silu_kernel<<<(MROWS*DI)/256, 256>>>(conv_w, conv_b);
    gemm(p_uconv, DI, p_WH+WBASE[1], p_WL+WBASE[1], nullptr, p_xdbl, MROWS, DTR+2*NN, DI, 0);
    gemm(p_xdbl, 80, p_WH+WBASE[2], p_WL+WBASE[2], dt_proj_b, p_dt, MROWS, DI, DTR, 2);  // softplus
    scan2_kernel<<<BB*4, 128>>>(A_log, Dp);
    gemm(p_ymam, DI, p_WH+WBASE[3], p_WL+WBASE[3], nullptr, p_mamba, MROWS, EE, DI, 0);

    // 3. attention branch (tensor-core FA2)
    gemm(p_seqs, EE, p_WH+WBASE[4], p_WL+WBASE[4], attn_in_b, p_qkv, MROWS, 3*EE, EE, 0);
    attn_mma_kernel<<<BB*HH*2, 256>>>();
    gemm(p_ctx, EE, p_WH+WBASE[5], p_WL+WBASE[5], attn_out_b, p_attno, MROWS, EE, EE, 0);

    // 4. fused add+LN1+combine
    add_ln_combine_kernel<<<MROWS/8, 256>>>(p_attno, p_seqs, ln1_g, ln1_b);

    // 5. FFN + fused add+LN2+logits
    gemm(p_comb, EE, p_WH+WBASE[6], p_WL+WBASE[6], ff_b1, p_ffh, MROWS, 4*EE, EE, 1);
    gemm(p_ffh, 4*EE, p_WH+WBASE[7], p_WL+WBASE[7], ff_b2, p_ff, MROWS, EE, 4*EE, 0);
    add_ln_logits_kernel<<<MROWS/8, 256>>>(p_ff, p_comb, ln2_g, ln2_b,
                                           pos_seqs, neg_seqs, item_emb, out);
}

// round 14
// speedup vs baseline: 1.0356x; 1.0356x over previous
#include <cuda_runtime.h>
#include <cuda_bf16.h>
#include <stdint.h>
#include <math.h>

// Problem dims
#define BB 64
#define LL 512
#define EE 256
#define HH 8
#define NN 32
#define DC 4
#define DI 512
#define DTR 16
#define MROWS (BB*LL)   // 32768

#define WTOT 614400     // total packed weight pairs across all 8 matrices
#define FR256 ((MROWS/16)*(256/16)*32)   // uint4 count for a [MROWS x 256] frag array

// ---------------- scratch (static device globals; no allocs) ----------------
__device__ float g_seqs  [MROWS*EE];
__device__ float g_xz    [MROWS*(2*DI)];
__device__ float g_uconv [MROWS*DI];
__device__ float g_xdbl  [MROWS*80];
__device__ float g_dt    [MROWS*DI];
__device__ float g_ymam  [MROWS*DI];
__device__ float g_mamba [MROWS*EE];
__device__ float g_qkv   [MROWS*(3*EE)];
__device__ float g_ctx   [MROWS*EE];
__device__ float g_attno [MROWS*EE];
__device__ float g_comb  [MROWS*EE];
__device__ float g_ffh   [MROWS*(4*EE)];
__device__ float g_ff    [MROWS*EE];
__device__ float g_gate  [BB];
__device__ __align__(16) unsigned g_WH[WTOT];
__device__ __align__(16) unsigned g_WL[WTOT];
// fragment-order bf16 hi/lo activations (A operands for psa GEMMs)
__device__ uint4 g_seqsH4[FR256];
__device__ uint4 g_seqsL4[FR256];
__device__ uint4 g_combH4[FR256];
__device__ uint4 g_combL4[FR256];

// ---------------- BF16 split helpers ----------------
__device__ __forceinline__ void split_bf16x2(float a, float b, unsigned& hi, unsigned& lo) {
    __nv_bfloat162 h = __floats2bfloat162_rn(a, b);   // .x = a (low 16 bits)
    float ra = a - __bfloat162float(h.x);
    float rb = b - __bfloat162float(h.y);
    __nv_bfloat162 l = __floats2bfloat162_rn(ra, rb);
    hi = *reinterpret_cast<unsigned*>(&h);
    lo = *reinterpret_cast<unsigned*>(&l);
}
__device__ __forceinline__ void mma_bf16(float c[4], const unsigned a[4], const unsigned b[2]) {
    asm volatile(
        "mma.sync.aligned.m16n8k16.row.col.f32.bf16.bf16.f32 "
        "{%0,%1,%2,%3},{%4,%5,%6,%7},{%8,%9},{%0,%1,%2,%3};"
        : "+f"(c[0]), "+f"(c[1]), "+f"(c[2]), "+f"(c[3])
        : "r"(a[0]), "r"(a[1]), "r"(a[2]), "r"(a[3]), "r"(b[0]), "r"(b[1]));
}

// store one bf16 hi/lo pair (elements e, e+1 of row) into a fragment-order array (K=256)
__device__ __forceinline__ void store_frag256(uint4* H, uint4* L, int row, int e,
                                              float v0, float v1) {
    unsigned hi, lo;
    split_bf16x2(v0, v1, hi, lo);
    int rr = row & 15, half = rr >> 3, gid = rr & 7;
    int kstep = e >> 4;
    int p = (e & 15) >> 1;
    int kq = p & 3, pq = p >> 2;
    int reg = half + 2*pq;
    int sig = kq*8 + ((gid + 2*kq) & 7);
    size_t idx = ((size_t)((row >> 4)*16 + kstep))*32 + sig;
    ((unsigned*)&H[idx])[reg] = hi;
    ((unsigned*)&L[idx])[reg] = lo;
}

// FMA-pipe exp (no MUFU): exp(x) clamped below at -80.
__device__ __forceinline__ float fexp(float x) {
    float t = fmaxf(x, -80.f) * 1.4426950408889634f;
    float z = t + 12582912.f;
    int   i = __float_as_int(z) - 0x4B400000;
    float f = t - (z - 12582912.f);
    float p =      1.3333558146e-3f;
    p = fmaf(p, f, 9.6181291076e-3f);
    p = fmaf(p, f, 5.5504108664e-2f);
    p = fmaf(p, f, 2.4022650696e-1f);
    p = fmaf(p, f, 6.9314718056e-1f);
    p = fmaf(p, f, 1.0f);
    return __int_as_float(__float_as_int(p) + (i << 23));
}

// ---------------- embedding + positional (+ fragment emission) ----------------
__global__ void embed_kernel(const int* __restrict__ log_seqs,
                             const float* __restrict__ item_emb,
                             const float* __restrict__ pos_emb) {
    int i = blockIdx.x * blockDim.x + threadIdx.x;   // over MROWS*128 pairs
    int row = i >> 7;
    int e   = (i & 127) * 2;
    int l   = row & (LL-1);
    int it  = __ldg(&log_seqs[row]);
    float2 ie = *(const float2*)&item_emb[(size_t)it*EE + e];
    float2 pe = *(const float2*)&pos_emb[l*EE + e];
    float v0 = ie.x * 16.0f + pe.x;
    float v1 = ie.y * 16.0f + pe.y;
    *(float2*)&g_seqs[(size_t)row*EE + e] = make_float2(v0, v1);
    store_frag256(g_seqsH4, g_seqsL4, row, e, v0, v1);
}

// ---------------- weight pre-split: W[N][K] fp32 -> fragment-order bf16 hi/lo ----
struct PSDesc {
    const float* W[8];
    int K[8];
    int cum[9];
};
__global__ void presplit_kernel(PSDesc ps) {
    int t = blockIdx.x * blockDim.x + threadIdx.x;   // global pair index
    if (t >= ps.cum[8]) return;
    int m = 0;
    #pragma unroll
    for (int i = 1; i < 8; i++) if (t >= ps.cum[i]) m = i;
    int p  = t - ps.cum[m];
    int K  = ps.K[m];
    int kh = K >> 1;
    int n  = p / kh;
    int kp = p - n*kh;
    int kstep = kp >> 3;
    int pp = kp & 7;
    int kq = pp & 3, khi = pp >> 2;
    int gid = n & 7, n8b = n >> 3;
    int sig = kq*8 + ((gid + 2*kq) & 7);
    int idx = ps.cum[m] + ((n8b*(K>>4) + kstep)*32 + sig)*2 + khi;
    const float* W = ps.W[m];
    int k = kp*2;
    unsigned hi, lo;
    split_bf16x2(W[(size_t)n*K + k], W[(size_t)n*K + k + 1], hi, lo);
    g_WH[idx] = hi;
    g_WL[idx] = lo;
}

// ---------------- tensor-core GEMM (3xBF16 m16n8k16, double-buffered,
// fragment-order smem; B pre-split; A either fp32-split (psa=0) or pre-split (psa=1))
// C = act(A[M,K](lda) * W[N,K]^T + bias); M%128==0, K%16==0, N%8==0.
__global__ __launch_bounds__(256, 2)
void gemm_bf16_kernel(const float* __restrict__ A, int lda,
                      const uint4* __restrict__ AHg,
                      const uint4* __restrict__ ALg,
                      int psa,
                      const unsigned* __restrict__ WH,
                      const unsigned* __restrict__ WL,
                      int nN8,
                      const float* __restrict__ bias,
                      float* __restrict__ C,
                      int M, int N, int K, int act) {
    __shared__ uint4 AH4[2][8][32];
    __shared__ uint4 AL4[2][8][32];
    __shared__ uint2 BH2[2][16][32];
    __shared__ uint2 BL2[2][16][32];

    int tid  = threadIdx.x;
    int lane = tid & 31;
    int wid  = tid >> 5;
    int wm = wid >> 2;
    int wn = wid & 3;
    int gid = lane >> 2;
    int kq  = lane & 3;
    int slot = kq*8 + ((gid + 2*kq) & 7);

    int m0 = blockIdx.y * 128;
    int n0 = blockIdx.x * 128;
    int nKt = K >> 4;

    // A producer coords (split path)
    int lr  = tid >> 1;
    int khi = tid & 1;
    int lcb = khi * 8;
    int am16b = lr >> 4;
    int pgid  = lr & 7;
    int ahalf = (lr >> 3) & 1;
    int regA  = ahalf + 2*khi;
    int s0 =      ((pgid    ) & 7);
    int s1 = 8  + ((pgid + 2) & 7);
    int s2 = 16 + ((pgid + 4) & 7);
    int s3 = 24 + ((pgid + 6) & 7);

    // A producer coords (psa path): one uint4 per array per thread per stage
    int pam  = tid >> 5;         // 0..7 m16 block
    int psig = tid & 31;         // slot
    size_t abase = ((size_t)(blockIdx.y*8 + pam)*nKt)*32 + psig;
    const float4* AH4g = (const float4*)AHg;
    const float4* AL4g = (const float4*)ALg;

    // B producer coords: 2 uint2 per thread per array
    int f0 = tid*2, f1 = f0+1;
    int nb0 = f0 >> 5, sg0 = f0 & 31;
    int nb1 = f1 >> 5, sg1 = f1 & 31;
    int bW = n0 >> 3;
    bool v0 = (bW + nb0) < nN8;
    bool v1 = (bW + nb1) < nN8;
    const uint2* WH2 = (const uint2*)WH;
    const uint2* WL2 = (const uint2*)WL;
    size_t wb0 = (size_t)(bW+nb0)*nKt*32 + sg0;
    size_t wb1 = (size_t)(bW+nb1)*nKt*32 + sg1;

    float acc[4][4][4];
    #pragma unroll
    for (int i=0;i<4;i++)
        #pragma unroll
        for (int j=0;j<4;j++)
            #pragma unroll
            for (int r=0;r<4;r++) acc[i][j][r]=0.f;

    const float* aptr = A + (size_t)(m0+lr)*lda + lcb;

    // prologue: stage 0
    float4 a4, a4b;
    if (psa) {
        a4  = AH4g[abase];
        a4b = AL4g[abase];
    } else {
        a4  = *(const float4*)aptr;
        a4b = *(const float4*)(aptr + 4);
    }
    uint2 bh0 = v0 ? WH2[wb0] : make_uint2(0u,0u);
    uint2 bh1 = v1 ? WH2[wb1] : make_uint2(0u,0u);
    uint2 bl0 = v0 ? WL2[wb0] : make_uint2(0u,0u);
    uint2 bl1 = v1 ? WL2[wb1] : make_uint2(0u,0u);
    if (psa) {
        *(float4*)&AH4[0][pam][psig] = a4;
        *(float4*)&AL4[0][pam][psig] = a4b;
    } else {
        unsigned h, l;
        split_bf16x2(a4.x,  a4.y,  h, l);
        ((unsigned*)&AH4[0][am16b][s0])[regA]=h; ((unsigned*)&AL4[0][am16b][s0])[regA]=l;
        split_bf16x2(a4.z,  a4.w,  h, l);
        ((unsigned*)&AH4[0][am16b][s1])[regA]=h; ((unsigned*)&AL4[0][am16b][s1])[regA]=l;
        split_bf16x2(a4b.x, a4b.y, h, l);
        ((unsigned*)&AH4[0][am16b][s2])[regA]=h; ((unsigned*)&AL4[0][am16b][s2])[regA]=l;
        split_bf16x2(a4b.z, a4b.w, h, l);
        ((unsigned*)&AH4[0][am16b][s3])[regA]=h; ((unsigned*)&AL4[0][am16b][s3])[regA]=l;
    }
    BH2[0][nb0][sg0]=bh0; BH2[0][nb1][sg1]=bh1;
    BL2[0][nb0][sg0]=bl0; BL2[0][nb1][sg1]=bl1;
    __syncthreads();

    int nIter = K >> 4;
    for (int it = 0; it < nIter; it++) {
        int s = it & 1;
        bool more = (it + 1) < nIter;

        if (more) {
            if (psa) {
                size_t o = (size_t)(it+1)*32;
                a4  = AH4g[abase + o];
                a4b = AL4g[abase + o];
            } else {
                int ko = (it+1) << 4;
                a4  = *(const float4*)(aptr + ko);
                a4b = *(const float4*)(aptr + ko + 4);
            }
            size_t o2 = (size_t)(it+1)*32;
            bh0 = v0 ? WH2[wb0 + o2] : make_uint2(0u,0u);
            bh1 = v1 ? WH2[wb1 + o2] : make_uint2(0u,0u);
            bl0 = v0 ? WL2[wb0 + o2] : make_uint2(0u,0u);
            bl1 = v1 ? WL2[wb1 + o2] : make_uint2(0u,0u);
        }

        unsigned fah[4][4];
        #pragma unroll
        for (int mi=0; mi<4; mi++) {
            uint4 v = AH4[s][wm*4+mi][slot];
            fah[mi][0]=v.x; fah[mi][1]=v.y; fah[mi][2]=v.z; fah[mi][3]=v.w;
        }
        unsigned fb[4][2];
        #pragma unroll
        for (int ni=0; ni<4; ni++) {
            uint2 v = BH2[s][wn*4+ni][slot];
            fb[ni][0]=v.x; fb[ni][1]=v.y;
        }
        #pragma unroll
        for (int mi=0; mi<4; mi++)
            #pragma unroll
            for (int ni=0; ni<4; ni++)
                mma_bf16(acc[mi][ni], fah[mi], fb[ni]);
        {
            unsigned fal[4][4];
            #pragma unroll
            for (int mi=0; mi<4; mi++) {
                uint4 v = AL4[s][wm*4+mi][slot];
                fal[mi][0]=v.x; fal[mi][1]=v.y; fal[mi][2]=v.z; fal[mi][3]=v.w;
            }
            #pragma unroll
            for (int mi=0; mi<4; mi++)
                #pragma unroll
                for (int ni=0; ni<4; ni++)
                    mma_bf16(acc[mi][ni], fal[mi], fb[ni]);
        }
        #pragma unroll
        for (int ni=0; ni<4; ni++) {
            uint2 v = BL2[s][wn*4+ni][slot];
            fb[ni][0]=v.x; fb[ni][1]=v.y;
        }
        #pragma unroll
        for (int mi=0; mi<4; mi++)
            #pragma unroll
            for (int ni=0; ni<4; ni++)
                mma_bf16(acc[mi][ni], fah[mi], fb[ni]);

        if (more) {
            int d = s ^ 1;
            if (psa) {
                *(float4*)&AH4[d][pam][psig] = a4;
                *(float4*)&AL4[d][pam][psig] = a4b;
            } else {
                unsigned h, l;
                split_bf16x2(a4.x,  a4.y,  h, l);
                ((unsigned*)&AH4[d][am16b][s0])[regA]=h; ((unsigned*)&AL4[d][am16b][s0])[regA]=l;
                split_bf16x2(a4.z,  a4.w,  h, l);
                ((unsigned*)&AH4[d][am16b][s1])[regA]=h; ((unsigned*)&AL4[d][am16b][s1])[regA]=l;
                split_bf16x2(a4b.x, a4b.y, h, l);
                ((unsigned*)&AH4[d][am16b][s2])[regA]=h; ((unsigned*)&AL4[d][am16b][s2])[regA]=l;
                split_bf16x2(a4b.z, a4b.w, h, l);
                ((unsigned*)&AH4[d][am16b][s3])[regA]=h; ((unsigned*)&AL4[d][am16b][s3])[regA]=l;
            }
            BH2[d][nb0][sg0]=bh0; BH2[d][nb1][sg1]=bh1;
            BL2[d][nb0][sg0]=bl0; BL2[d][nb1][sg1]=bl1;
        }
        __syncthreads();
    }

    #pragma unroll
    for (int mi=0; mi<4; mi++) {
        int r = m0 + wm*64 + mi*16 + gid;
        #pragma unroll
        for (int ni=0; ni<4; ni++) {
            int c = n0 + wn*32 + ni*8 + kq*2;
            if (c < N) {
                float v0e = acc[mi][ni][0], v1e = acc[mi][ni][1];
                float v2e = acc[mi][ni][2], v3e = acc[mi][ni][3];
                if (bias) {
                    float b0 = bias[c], b1 = bias[c+1];
                    v0e += b0; v1e += b1; v2e += b0; v3e += b1;
                }
                if (act == 1) {
                    v0e=fmaxf(v0e,0.f); v1e=fmaxf(v1e,0.f); v2e=fmaxf(v2e,0.f); v3e=fmaxf(v3e,0.f);
                } else if (act == 2) {
                    v0e = (v0e>20.f)?v0e:log1pf(__expf(v0e));
                    v1e = (v1e>20.f)?v1e:log1pf(__expf(v1e));
                    v2e = (v2e>20.f)?v2e:log1pf(__expf(v2e));
                    v3e = (v3e>20.f)?v3e:log1pf(__expf(v3e));
                }
                *(float2*)(C + (size_t)r*N + c)       = make_float2(v0e, v1e);
                *(float2*)(C + (size_t)(r+8)*N + c)   = make_float2(v2e, v3e);
            }
        }
    }
}

// ---------------- causal depthwise conv (DC=4) + SiLU ----------------
__global__ void conv_silu_kernel(const float* __restrict__ conv_w,
                                 const float* __restrict__ conv_b) {
    int i = blockIdx.x * blockDim.x + threadIdx.x;
    int row = i >> 9;
    int d   = i & (DI-1);
    int b   = row >> 9;
    int l   = row & (LL-1);
    float acc = conv_b[d];
    #pragma unroll
    for (int k=0;k<DC;k++) {
        int ll = l - (DC-1) + k;
        if (ll >= 0)
            acc = fmaf(g_xz[(size_t)((b<<9)+ll)*(2*DI) + d], conv_w[d*DC + k], acc);
    }
    float s = acc / (1.f + __expf(-acc));
    g_uconv[i] = s;
}

// ---------------- selective scan v2 ----------------
#define TCH 16
__global__ __launch_bounds__(128)
void scan2_kernel(const float* __restrict__ A_log,
                  const float* __restrict__ Dp) {
    __shared__ float sBC[TCH][64];
    int b = blockIdx.x >> 2;
    int q = blockIdx.x & 3;
    int d = q*128 + threadIdx.x;
    int brow = b << 9;

    float h[32];
    #pragma unroll
    for (int n=0;n<32;n++) h[n]=0.f;
    float dpv = Dp[d];

    bool fast = true;
    #pragma unroll
    for (int n=0;n<32;n++) {
        float a = -__expf(A_log[d*NN + n]);
        if (fabsf(a + (float)(n+1)) > 1e-3f*(float)(n+1)) fast = false;
    }

    for (int t0=0; t0<LL; t0+=TCH) {
        __syncthreads();
        #pragma unroll
        for (int it=0; it<2; it++) {
            int p  = it*128 + threadIdx.x;
            int t  = p >> 4;
            int j  = (p & 15) * 4;
            *(float4*)&sBC[t][j] =
                *(const float4*)&g_xdbl[(size_t)(brow+t0+t)*80 + DTR + j];
        }
        __syncthreads();

        if (fast) {
            #pragma unroll 4
            for (int tt=0; tt<TCH; tt++) {
                int row = brow + t0 + tt;
                float dtv = g_dt   [(size_t)row*DI + d];
                float uv  = g_uconv[(size_t)row*DI + d];
                float p  = __expf(-dtv);
                float du = dtv * uv;
                float w  = 1.f;
                float y0=0.f,y1=0.f,y2=0.f,y3=0.f;
                #pragma unroll
                for (int n=0;n<32;n+=4) {
                    w *= p; h[n  ]=fmaf(w,h[n  ],du*sBC[tt][n  ]); y0=fmaf(h[n  ],sBC[tt][32+n  ],y0);
                    w *= p; h[n+1]=fmaf(w,h[n+1],du*sBC[tt][n+1]); y1=fmaf(h[n+1],sBC[tt][33+n  ],y1);
                    w *= p; h[n+2]=fmaf(w,h[n+2],du*sBC[tt][n+2]); y2=fmaf(h[n+2],sBC[tt][34+n  ],y2);
                    w *= p; h[n+3]=fmaf(w,h[n+3],du*sBC[tt][n+3]); y3=fmaf(h[n+3],sBC[tt][35+n  ],y3);
                }
                float y = (y0+y1)+(y2+y3);
                float z  = g_xz[(size_t)row*(2*DI) + DI + d];
                float sz = z / (1.f + __expf(-z));
                g_ymam[(size_t)row*DI + d] = (y + uv*dpv) * sz;
            }
        } else {
            for (int tt=0; tt<TCH; tt++) {
                int row = brow + t0 + tt;
                float dtv = g_dt   [(size_t)row*DI + d];
                float uv  = g_uconv[(size_t)row*DI + d];
                float du = dtv * uv;
                float y = 0.f;
                #pragma unroll
                for (int n=0;n<32;n++) {
                    float a = -__expf(A_log[d*NN + n]);
                    float e = __expf(dtv * a);
                    h[n] = fmaf(e, h[n], du*sBC[tt][n]);
                    y = fmaf(h[n], sBC[tt][32+n], y);
                }
                float z  = g_xz[(size_t)row*(2*DI) + DI + d];
                float sz = z / (1.f + __expf(-z));
                g_ymam[(size_t)row*DI + d] = (y + uv*dpv) * sz;
            }
        }
    }
}

// ---------------- attention: FA2-style bf16 mma ----------------
__global__ __launch_bounds__(256)
void attn_mma_kernel() {
    __shared__ uint2 KH[2][4][32], KL[2][4][32];
    __shared__ uint2 VH[2][4][32], VL[2][4][32];

    int bh = blockIdx.x >> 1;
    int qh = blockIdx.x & 1;
    int b  = bh >> 3, h = bh & 7;
    int brow = b << 9;
    int tid = threadIdx.x;
    int w = tid >> 5, lane = tid & 31;
    int gid = lane >> 2, kq = lane & 3;
    int slot = kq*8 + ((gid + 2*kq) & 7);
    const float scale = 0.17677669529663687f;

    int qb = qh*256 + w*32;
    unsigned qa_h[2][2][4], qa_l[2][2][4];
    #pragma unroll
    for (int mi=0; mi<2; mi++) {
        int r0 = brow + qb + mi*16 + gid;
        const float* q0 = g_qkv + (size_t)r0*(3*EE) + h*32;
        const float* q1 = q0 + (size_t)8*(3*EE);
        #pragma unroll
        for (int ks=0; ks<2; ks++) {
            int dA = 16*ks + 2*kq;
            float2 v0 = *(const float2*)(q0 + dA);
            float2 v1 = *(const float2*)(q1 + dA);
            float2 v2 = *(const float2*)(q0 + dA + 8);
            float2 v3 = *(const float2*)(q1 + dA + 8);
            split_bf16x2(v0.x*scale, v0.y*scale, qa_h[mi][ks][0], qa_l[mi][ks][0]);
            split_bf16x2(v1.x*scale, v1.y*scale, qa_h[mi][ks][1], qa_l[mi][ks][1]);
            split_bf16x2(v2.x*scale, v2.y*scale, qa_h[mi][ks][2], qa_l[mi][ks][2]);
            split_bf16x2(v3.x*scale, v3.y*scale, qa_h[mi][ks][3], qa_l[mi][ks][3]);
        }
    }

    float o[2][4][4];
    #pragma unroll
    for (int mi=0;mi<2;mi++)
        #pragma unroll
        for (int vb=0;vb<4;vb++)
            #pragma unroll
            for (int c=0;c<4;c++) o[mi][vb][c]=0.f;
    float mrun[2][2] = {{-1e30f,-1e30f},{-1e30f,-1e30f}};
    float lrun[2][2] = {{0.f,0.f},{0.f,0.f}};

    int pkn  = tid >> 3;
    int pkd0 = (tid & 7) * 4;
    int pkks = pkd0 >> 4;
    int pkp0 = (pkd0 & 15) >> 1;
    int pkkq0 = pkp0 & 3, pkkhi = pkp0 >> 2;
    int pkbn = pkn >> 3, pkg = pkn & 7;
    int pksA = pkkq0*8 + ((pkg + 2*pkkq0) & 7);
    int pksB = (pkkq0+1)*8 + ((pkg + 2*(pkkq0+1)) & 7);
    int pvp  = tid >> 4;
    int pvd0 = (tid & 15) * 2;
    int pvks = pvp >> 3;
    int pvq  = (pvp & 7) & 3, pvkhi = (pvp & 7) >> 2;
    int pvbnA = pvd0 >> 3,      pvsA = pvq*8 + (((pvd0 & 7) + 2*pvq) & 7);
    int pvbnB = (pvd0+1) >> 3,  pvsB = pvq*8 + ((((pvd0+1) & 7) + 2*pvq) & 7);

    for (int kt = 0; kt < 16; kt++) {
        __syncthreads();
        {
            const float* kp = g_qkv + (size_t)(brow + kt*32 + pkn)*(3*EE) + EE + h*32 + pkd0;
            float4 kv = *(const float4*)kp;
            unsigned hi, lo;
            split_bf16x2(kv.x, kv.y, hi, lo);
            ((unsigned*)&KH[pkks][pkbn][pksA])[pkkhi]=hi; ((unsigned*)&KL[pkks][pkbn][pksA])[pkkhi]=lo;
            split_bf16x2(kv.z, kv.w, hi, lo);
            ((unsigned*)&KH[pkks][pkbn][pksB])[pkkhi]=hi; ((unsigned*)&KL[pkks][pkbn][pksB])[pkkhi]=lo;
        }
        {
            const float* v0p = g_qkv + (size_t)(brow + kt*32 + 2*pvp)*(3*EE) + 2*EE + h*32 + pvd0;
            const float* v1p = v0p + 3*EE;
            float2 va = *(const float2*)v0p;
            float2 vb = *(const float2*)v1p;
            unsigned hi, lo;
            split_bf16x2(va.x, vb.x, hi, lo);
            ((unsigned*)&VH[pvks][pvbnA][pvsA])[pvkhi]=hi; ((unsigned*)&VL[pvks][pvbnA][pvsA])[pvkhi]=lo;
            split_bf16x2(va.y, vb.y, hi, lo);
            ((unsigned*)&VH[pvks][pvbnB][pvsB])[pvkhi]=hi; ((unsigned*)&VL[pvks][pvbnB][pvsB])[pvkhi]=lo;
        }
        __syncthreads();

        float sa[2][4][4];
        #pragma unroll
        for (int mi=0;mi<2;mi++)
            #pragma unroll
            for (int bn=0;bn<4;bn++)
                #pragma unroll
                for (int c=0;c<4;c++) sa[mi][bn][c]=0.f;
        #pragma unroll
        for (int bn=0; bn<4; bn++) {
            #pragma unroll
            for (int ks=0; ks<2; ks++) {
                uint2 kh2 = KH[ks][bn][slot];
                unsigned kh[2] = {kh2.x, kh2.y};
                uint2 kl2 = KL[ks][bn][slot];
                unsigned kl[2] = {kl2.x, kl2.y};
                #pragma unroll
                for (int mi=0; mi<2; mi++) {
                    mma_bf16(sa[mi][bn], qa_h[mi][ks], kh);
                    mma_bf16(sa[mi][bn], qa_l[mi][ks], kh);
                    mma_bf16(sa[mi][bn], qa_h[mi][ks], kl);
                }
            }
        }

        #pragma unroll
        for (int mi=0; mi<2; mi++) {
            #pragma unroll
            for (int rr=0; rr<2; rr++) {
                int c0 = rr*2;
                float mx = -1e30f;
                #pragma unroll
                for (int bn=0; bn<4; bn++) {
                    mx = fmaxf(mx, sa[mi][bn][c0]);
                    mx = fmaxf(mx, sa[mi][bn][c0+1]);
                }
                mx = fmaxf(mx, __shfl_xor_sync(0xffffffffu, mx, 1));
                mx = fmaxf(mx, __shfl_xor_sync(0xffffffffu, mx, 2));
                float mnew = fmaxf(mrun[mi][rr], mx);
                float corr = fexp(mrun[mi][rr] - mnew);
                mrun[mi][rr] = mnew;
                float psum = 0.f;
                #pragma unroll
                for (int bn=0; bn<4; bn++) {
                    float p0 = fexp(sa[mi][bn][c0]   - mnew);
                    float p1 = fexp(sa[mi][bn][c0+1] - mnew);
                    sa[mi][bn][c0]   = p0;
                    sa[mi][bn][c0+1] = p1;
                    psum += p0 + p1;
                }
                psum += __shfl_xor_sync(0xffffffffu, psum, 1);
                psum += __shfl_xor_sync(0xffffffffu, psum, 2);
                lrun[mi][rr] = lrun[mi][rr]*corr + psum;
                #pragma unroll
                for (int vb=0; vb<4; vb++) {
                    o[mi][vb][c0]   *= corr;
                    o[mi][vb][c0+1] *= corr;
                }
            }
        }

        #pragma unroll
        for (int mi=0; mi<2; mi++) {
            #pragma unroll
            for (int j=0; j<2; j++) {
                unsigned pa_h[4], pa_l[4];
                split_bf16x2(sa[mi][2*j  ][0], sa[mi][2*j  ][1], pa_h[0], pa_l[0]);
                split_bf16x2(sa[mi][2*j  ][2], sa[mi][2*j  ][3], pa_h[1], pa_l[1]);
                split_bf16x2(sa[mi][2*j+1][0], sa[mi][2*j+1][1], pa_h[2], pa_l[2]);
                split_bf16x2(sa[mi][2*j+1][2], sa[mi][2*j+1][3], pa_h[3], pa_l[3]);
                #pragma unroll
                for (int vb=0; vb<4; vb++) {
                    uint2 vh2 = VH[j][vb][slot];
                    unsigned vh[2] = {vh2.x, vh2.y};
                    mma_bf16(o[mi][vb], pa_h, vh);
                    mma_bf16(o[mi][vb], pa_l, vh);
                    uint2 vl2 = VL[j][vb][slot];
                    unsigned vl[2] = {vl2.x, vl2.y};
                    mma_bf16(o[mi][vb], pa_h, vl);
                }
            }
        }
    }

    #pragma unroll
    for (int mi=0; mi<2; mi++) {
        float inv0 = 1.f / lrun[mi][0];
        float inv1 = 1.f / lrun[mi][1];
        int r0 = brow + qb + mi*16 + gid;
        float* c0p = g_ctx + (size_t)r0*EE + h*32;
        float* c1p = c0p + (size_t)8*EE;
        #pragma unroll
        for (int vb=0; vb<4; vb++) {
            int cc = vb*8 + kq*2;
            *(float2*)(c0p + cc) = make_float2(o[mi][vb][0]*inv0, o[mi][vb][1]*inv0);
            *(float2*)(c1p + cc) = make_float2(o[mi][vb][2]*inv1, o[mi][vb][3]*inv1);
        }
    }
}

// ---------------- fused: add + LN(ln1) + gated combine -> g_comb (+frags) ----------------
__global__ void add_ln_combine_kernel(const float* __restrict__ x, const float* __restrict__ res,
                                      const float* __restrict__ g, const float* __restrict__ bta) {
    int row  = blockIdx.x * (blockDim.x >> 5) + (threadIdx.x >> 5);
    int lane = threadIdx.x & 31;
    const float4* xp = (const float4*)(x   + (size_t)row*EE);
    const float4* rp = (const float4*)(res + (size_t)row*EE);
    float v[8];
    float4 a0 = xp[lane],     b0 = rp[lane];
    float4 a1 = xp[lane+32],  b1 = rp[lane+32];
    v[0]=a0.x+b0.x; v[1]=a0.y+b0.y; v[2]=a0.z+b0.z; v[3]=a0.w+b0.w;
    v[4]=a1.x+b1.x; v[5]=a1.y+b1.y; v[6]=a1.z+b1.z; v[7]=a1.w+b1.w;
    float s=0.f, s2=0.f;
    #pragma unroll
    for (int i=0;i<8;i++){ s += v[i]; s2 = fmaf(v[i], v[i], s2); }
    #pragma unroll
    for (int off=16; off; off>>=1) {
        s  += __shfl_xor_sync(0xffffffffu, s,  off);
        s2 += __shfl_xor_sync(0xffffffffu, s2, off);
    }
    float mean = s * (1.f/EE);
    float var  = s2 * (1.f/EE) - mean*mean;
    float rstd = rsqrtf(var + 1e-6f);
    const float4* gp = (const float4*)g;
    const float4* bp = (const float4*)bta;
    float4 g0=gp[lane], g1=gp[lane+32], c0=bp[lane], c1=bp[lane+32];
    const float4* mp = (const float4*)(g_mamba + (size_t)row*EE);
    float4 m0 = mp[lane], m1 = mp[lane+32];
    float w = g_gate[row >> 9];
    float iw = 1.f - w;
    float4* op = (float4*)(g_comb + (size_t)row*EE);
    float4 o0, o1;
    o0.x = w*m0.x + iw*((v[0]-mean)*rstd*g0.x+c0.x);
    o0.y = w*m0.y + iw*((v[1]-mean)*rstd*g0.y+c0.y);
    o0.z = w*m0.z + iw*((v[2]-mean)*rstd*g0.z+c0.z);
    o0.w = w*m0.w + iw*((v[3]-mean)*rstd*g0.w+c0.w);
    o1.x = w*m1.x + iw*((v[4]-mean)*rstd*g1.x+c1.x);
    o1.y = w*m1.y + iw*((v[5]-mean)*rstd*g1.y+c1.y);
    o1.z = w*m1.z + iw*((v[6]-mean)*rstd*g1.z+c1.z);
    o1.w = w*m1.w + iw*((v[7]-mean)*rstd*g1.w+c1.w);
    op[lane]    = o0;
    op[lane+32] = o1;
    // fragment emission for ff1 (A operand)
    int e0 = lane*4;
    store_frag256(g_combH4, g_combL4, row, e0,       o0.x, o0.y);
    store_frag256(g_combH4, g_combL4, row, e0+2,     o0.z, o0.w);
    store_frag256(g_combH4, g_combL4, row, e0+128,   o1.x, o1.y);
    store_frag256(g_combH4, g_combL4, row, e0+130,   o1.z, o1.w);
}

// ---------------- fused: add + LN(ln2) + pos/neg logits -> out ----------------
__global__ void add_ln_logits_kernel(const float* __restrict__ x, const float* __restrict__ res,
                                     const float* __restrict__ g, const float* __restrict__ bta,
                                     const int* __restrict__ pos, const int* __restrict__ neg,
                                     const float* __restrict__ item_emb, float* __restrict__ out) {
    int row  = blockIdx.x * (blockDim.x >> 5) + (threadIdx.x >> 5);
    int lane = threadIdx.x & 31;
    const float4* xp = (const float4*)(x   + (size_t)row*EE);
    const float4* rp = (const float4*)(res + (size_t)row*EE);
    float v[8];
    float4 a0 = xp[lane],     b0 = rp[lane];
    float4 a1 = xp[lane+32],  b1 = rp[lane+32];
    v[0]=a0.x+b0.x; v[1]=a0.y+b0.y; v[2]=a0.z+b0.z; v[3]=a0.w+b0.w;
    v[4]=a1.x+b1.x; v[5]=a1.y+b1.y; v[6]=a1.z+b1.z; v[7]=a1.w+b1.w;
    float s=0.f, s2=0.f;
    #pragma unroll
    for (int i=0;i<8;i++){ s += v[i]; s2 = fmaf(v[i], v[i], s2); }
    #pragma unroll
    for (int off=16; off; off>>=1) {
        s  += __shfl_xor_sync(0xffffffffu, s,  off);
        s2 += __shfl_xor_sync(0xffffffffu, s2, off);
    }
    float mean = s * (1.f/EE);
    float var  = s2 * (1.f/EE) - mean*mean;
    float rstd = rsqrtf(var + 1e-6f);
    const float4* gp = (const float4*)g;
    const float4* bp = (const float4*)bta;
    float4 g0=gp[lane], g1=gp[lane+32], c0=bp[lane], c1=bp[lane+32];
    float f[8];
    f[0]=(v[0]-mean)*rstd*g0.x+c0.x; f[1]=(v[1]-mean)*rstd*g0.y+c0.y;
    f[2]=(v[2]-mean)*rstd*g0.z+c0.z; f[3]=(v[3]-mean)*rstd*g0.w+c0.w;
    f[4]=(v[4]-mean)*rstd*g1.x+c1.x; f[5]=(v[5]-mean)*rstd*g1.y+c1.y;
    f[6]=(v[6]-mean)*rstd*g1.z+c1.z; f[7]=(v[7]-mean)*rstd*g1.w+c1.w;
    int pi = __ldg(&pos[row]), ni = __ldg(&neg[row]);
    const float4* pe = (const float4*)(item_emb + (size_t)pi*EE);
    const float4* ne = (const float4*)(item_emb + (size_t)ni*EE);
    float4 p0 = pe[lane], p1 = pe[lane+32];
    float4 n0 = ne[lane], n1 = ne[lane+32];
    float dp = f[0]*p0.x+f[1]*p0.y+f[2]*p0.z+f[3]*p0.w
             + f[4]*p1.x+f[5]*p1.y+f[6]*p1.z+f[7]*p1.w;
    float dn = f[0]*n0.x+f[1]*n0.y+f[2]*n0.z+f[3]*n0.w
             + f[4]*n1.x+f[5]*n1.y+f[6]*n1.z+f[7]*n1.w;
    #pragma unroll
    for (int off=16; off; off>>=1) {
        dp += __shfl_xor_sync(0xffffffffu, dp, off);
        dn += __shfl_xor_sync(0xffffffffu, dn, off);
    }
    if (lane == 0) {
        out[row]         = dp;
        out[MROWS + row] = dn;
    }
}

// ---------------- gate ----------------
__global__ void gate_kernel(const float* __restrict__ mw_w, const float* __restrict__ mw_b) {
    int b = blockIdx.x;
    int e = threadIdx.x;
    float s = 0.f;
    for (int l=0;l<LL;l++) s += g_seqs[(size_t)((b<<9)+l)*EE + e];
    s = (s * (1.f/LL)) * mw_w[e];
    __shared__ float red[256];
    red[e] = s; __syncthreads();
    for (int st=128; st; st>>=1) { if (e < st) red[e] += red[e+st]; __syncthreads(); }
    if (e == 0) g_gate[b] = 1.f / (1.f + __expf(-(red[0] + mw_b[0])));
}

// ---------------- host ----------------
static float* symaddr(const void* sym) {
    void* p = nullptr;
    cudaGetSymbolAddress(&p, sym);
    return (float*)p;
}

// matrix order: in_proj, x_proj, dt_proj, out_proj, attn_in, attn_out, ff1, ff2
static const int WBASE[9] = {0, 131072, 151552, 155648, 221184, 319488, 352256, 483328, 614400};

static void gemm(const float* A, int lda,
                 const uint4* AHg, const uint4* ALg, int psa,
                 const unsigned* WH, const unsigned* WL,
                 const float* bias, float* C, int M, int N, int K, int act) {
    dim3 grid((N + 127) / 128, M / 128);
    gemm_bf16_kernel<<<grid, 256>>>(A, lda, AHg, ALg, psa, WH, WL, N >> 3, bias, C, M, N, K, act);
}

extern "C" void kernel_launch(void* const* d_in, const int* in_sizes, int n_in,
                              void* d_out, int out_size) {
    const int*   log_seqs  = (const int*)  d_in[1];
    const int*   pos_seqs  = (const int*)  d_in[2];
    const int*   neg_seqs  = (const int*)  d_in[3];
    const float* item_emb  = (const float*)d_in[4];
    const float* pos_emb   = (const float*)d_in[5];
    const float* in_proj_w = (const float*)d_in[6];
    const float* conv_w    = (const float*)d_in[7];
    const float* conv_b    = (const float*)d_in[8];
    const float* x_proj_w  = (const float*)d_in[9];
    const float* dt_proj_w = (const float*)d_in[10];
    const float* dt_proj_b = (const float*)d_in[11];
    const float* A_log     = (const float*)d_in[12];
    const float* Dp        = (const float*)d_in[13];
    const float* out_proj_w= (const float*)d_in[14];
    const float* attn_in_w = (const float*)d_in[15];
    const float* attn_in_b = (const float*)d_in[16];
    const float* attn_out_w= (const float*)d_in[17];
    const float* attn_out_b= (const float*)d_in[18];
    const float* ln1_g     = (const float*)d_in[19];
    const float* ln1_b     = (const float*)d_in[20];
    const float* mw_w      = (const float*)d_in[21];
    const float* mw_b      = (const float*)d_in[22];
    const float* ff_w1     = (const float*)d_in[23];
    const float* ff_b1     = (const float*)d_in[24];
    const float* ff_w2     = (const float*)d_in[25];
    const float* ff_b2     = (const float*)d_in[26];
    const float* ln2_g     = (const float*)d_in[27];
    const float* ln2_b     = (const float*)d_in[28];
    float* out = (float*)d_out;

    float* p_seqs   = symaddr(g_seqs);
    float* p_xz     = symaddr(g_xz);
    float* p_uconv  = symaddr(g_uconv);
    float* p_xdbl   = symaddr(g_xdbl);
    float* p_dt     = symaddr(g_dt);
    float* p_ymam   = symaddr(g_ymam);
    float* p_mamba  = symaddr(g_mamba);
    float* p_qkv    = symaddr(g_qkv);
    float* p_ctx    = symaddr(g_ctx);
    float* p_attno  = symaddr(g_attno);
    float* p_comb   = symaddr(g_comb);
    float* p_ffh    = symaddr(g_ffh);
    float* p_ff     = symaddr(g_ff);
    unsigned* p_WH  = (unsigned*)symaddr(g_WH);
    unsigned* p_WL  = (unsigned*)symaddr(g_WL);
    uint4* p_sH = (uint4*)symaddr(g_seqsH4);
    uint4* p_sL = (uint4*)symaddr(g_seqsL4);
    uint4* p_cH = (uint4*)symaddr(g_combH4);
    uint4* p_cL = (uint4*)symaddr(g_combL4);

    // 0. pre-split all weights into fragment-order bf16 hi/lo
    PSDesc ps;
    ps.W[0]=in_proj_w;  ps.K[0]=256;
    ps.W[1]=x_proj_w;   ps.K[1]=512;
    ps.W[2]=dt_proj_w;  ps.K[2]=16;
    ps.W[3]=out_proj_w; ps.K[3]=512;
    ps.W[4]=attn_in_w;  ps.K[4]=256;
    ps.W[5]=attn_out_w; ps.K[5]=256;
    ps.W[6]=ff_w1;      ps.K[6]=256;
    ps.W[7]=ff_w2;      ps.K[7]=1024;
    for (int i=0;i<9;i++) ps.cum[i] = WBASE[i];
    presplit_kernel<<<(WTOT + 255)/256, 256>>>(ps);

    // 1. embedding + positional (emits fp32 + frag); gate
    embed_kernel<<<(MROWS*128)/256, 256>>>(log_seqs, item_emb, pos_emb);
    gate_kernel<<<BB, 256>>>(mw_w, mw_b);

    // 2. Mamba branch
    gemm(p_seqs, EE, p_sH, p_sL, 1, p_WH+WBASE[0], p_WL+WBASE[0], nullptr, p_xz, MROWS, 2*DI, EE, 0);
    conv_silu_kernel<<<(MROWS*DI)/256, 256>>>(conv_w, conv_b);
    gemm(p_uconv, DI, nullptr, nullptr, 0, p_WH+WBASE[1], p_WL+WBASE[1], nullptr, p_xdbl, MROWS, DTR+2*NN, DI, 0);
    gemm(p_xdbl, 80, nullptr, nullptr, 0, p_WH+WBASE[2], p_WL+WBASE[2], dt_proj_b, p_dt, MROWS, DI, DTR, 2);
    scan2_kernel<<<BB*4, 128>>>(A_log, Dp);
    gemm(p_ymam, DI, nullptr, nullptr, 0, p_WH+WBASE[3], p_WL+WBASE[3], nullptr, p_mamba, MROWS, EE, DI, 0);

    // 3. attention branch (tensor-core FA2)
    gemm(p_seqs, EE, p_sH, p_sL, 1, p_WH+WBASE[4], p_WL+WBASE[4], attn_in_b, p_qkv, MROWS, 3*EE, EE, 0);
    attn_mma_kernel<<<BB*HH*2, 256>>>();
    gemm(p_ctx, EE, nullptr, nullptr, 0, p_WH+WBASE[5], p_WL+WBASE[5], attn_out_b, p_attno, MROWS, EE, EE, 0);

    // 4. fused add+LN1+combine (emits fp32 + frag)
    add_ln_combine_kernel<<<MROWS/8, 256>>>(p_attno, p_seqs, ln1_g, ln1_b);

    // 5. FFN + fused add+LN2+logits
    gemm(p_comb, EE, p_cH, p_cL, 1, p_WH+WBASE[6], p_WL+WBASE[6], ff_b1, p_ffh, MROWS, 4*EE, EE, 1);
    gemm(p_ffh, 4*EE, nullptr, nullptr, 0, p_WH+WBASE[7], p_WL+WBASE[7], ff_b2, p_ff, MROWS, EE, 4*EE, 0);
    add_ln_logits_kernel<<<MROWS/8, 256>>>(p_ff, p_comb, ln2_g, ln2_b,
                                           pos_seqs, neg_seqs, item_emb, out);
}

// round 15
// speedup vs baseline: 1.0871x; 1.0497x over previous
#include <cuda_runtime.h>
#include <cuda_bf16.h>
#include <stdint.h>
#include <math.h>

// Problem dims
#define BB 64
#define LL 512
#define EE 256
#define HH 8
#define NN 32
#define DC 4
#define DI 512
#define DTR 16
#define MROWS (BB*LL)   // 32768

#define WTOT 614400     // total packed weight pairs across all 8 matrices

// ---------------- scratch (static device globals; no allocs) ----------------
__device__ float g_seqs  [MROWS*EE];
__device__ float g_xz    [MROWS*(2*DI)];
__device__ float g_uconv [MROWS*DI];
__device__ float g_xdbl  [MROWS*80];
__device__ float g_dt    [MROWS*DI];
__device__ float g_ymam  [MROWS*DI];
__device__ float g_mamba [MROWS*EE];
__device__ float g_qkv   [MROWS*(3*EE)];
__device__ float g_ctx   [MROWS*EE];
__device__ float g_attno [MROWS*EE];
__device__ float g_comb  [MROWS*EE];
__device__ float g_ffh   [MROWS*(4*EE)];
__device__ float g_ff    [MROWS*EE];
__device__ float g_gate  [BB];
__device__ __align__(16) unsigned g_WH[WTOT];
__device__ __align__(16) unsigned g_WL[WTOT];

// ---------------- fast transcendentals (FMA pipe, no MUFU) ----------------
// two-sided exp, clamped to +-87
__device__ __forceinline__ float fexp(float x) {
    float t = fminf(fmaxf(x, -87.f), 87.f) * 1.4426950408889634f;
    float z = t + 12582912.f;                       // round to nearest int
    int   i = __float_as_int(z) - 0x4B400000;
    float f = t - (z - 12582912.f);                 // f in [-0.5, 0.5]
    float p =      1.3333558146e-3f;
    p = fmaf(p, f, 9.6181291076e-3f);
    p = fmaf(p, f, 5.5504108664e-2f);
    p = fmaf(p, f, 2.4022650696e-1f);
    p = fmaf(p, f, 6.9314718056e-1f);
    p = fmaf(p, f, 1.0f);
    return __int_as_float(__float_as_int(p) + (i << 23));
}
// reciprocal for y > 0: bit-trick seed + 3 Newton iterations (FMA only)
__device__ __forceinline__ float frcp(float y) {
    float x = __int_as_float(0x7EF311C3 - __float_as_int(y));
    x = x * fmaf(-y, x, 2.f);
    x = x * fmaf(-y, x, 2.f);
    x = x * fmaf(-y, x, 2.f);
    return x;
}
__device__ __forceinline__ float fsigmoid(float z) {
    float e = fexp(-fabsf(z));
    float s = frcp(1.f + e);          // sigmoid(|z|), e <= 1
    return (z >= 0.f) ? s : 1.f - s;
}
__device__ __forceinline__ float fsilu(float x) { return x * fsigmoid(x); }
// softplus = log1p(exp(v)); log via exponent split + atanh series
__device__ __forceinline__ float fsoftplus(float v) {
    if (v > 20.f) return v;
    float e = fexp(v);
    float y = 1.f + e;
    int   b = __float_as_int(y);
    int   ie = (b >> 23) - 127;
    float m = __int_as_float((b & 0x7FFFFF) | 0x3F800000);   // [1,2)
    float t = (m - 1.f) * frcp(m + 1.f);
    float u = t * t;
    float P = fmaf(u, fmaf(u, fmaf(u, 0.14285714f, 0.2f), 0.33333333f), 1.f);
    return fmaf((float)ie, 0.6931471805599453f, 2.f * t * P);
}

// ---------------- embedding + positional ----------------
__global__ void embed_kernel(const int* __restrict__ log_seqs,
                             const float* __restrict__ item_emb,
                             const float* __restrict__ pos_emb) {
    int i = blockIdx.x * blockDim.x + threadIdx.x;   // over MROWS*EE
    int row = i >> 8;           // b*L + l
    int e   = i & 255;
    int l   = row & (LL-1);
    int it  = __ldg(&log_seqs[row]);
    g_seqs[i] = item_emb[(size_t)it*EE + e] * 16.0f + pos_emb[l*EE + e];
}

// ---------------- BF16 split helpers ----------------
__device__ __forceinline__ void split_bf16x2(float a, float b, unsigned& hi, unsigned& lo) {
    __nv_bfloat162 h = __floats2bfloat162_rn(a, b);   // .x = a (low 16 bits)
    float ra = a - __bfloat162float(h.x);
    float rb = b - __bfloat162float(h.y);
    __nv_bfloat162 l = __floats2bfloat162_rn(ra, rb);
    hi = *reinterpret_cast<unsigned*>(&h);
    lo = *reinterpret_cast<unsigned*>(&l);
}
__device__ __forceinline__ void mma_bf16(float c[4], const unsigned a[4], const unsigned b[2]) {
    asm volatile(
        "mma.sync.aligned.m16n8k16.row.col.f32.bf16.bf16.f32 "
        "{%0,%1,%2,%3},{%4,%5,%6,%7},{%8,%9},{%0,%1,%2,%3};"
        : "+f"(c[0]), "+f"(c[1]), "+f"(c[2]), "+f"(c[3])
        : "r"(a[0]), "r"(a[1]), "r"(a[2]), "r"(a[3]), "r"(b[0]), "r"(b[1]));
}

// ---------------- weight pre-split: W[N][K] fp32 -> fragment-order bf16 hi/lo ----
struct PSDesc {
    const float* W[8];
    int K[8];
    int cum[9];
};
__global__ void presplit_kernel(PSDesc ps) {
    int t = blockIdx.x * blockDim.x + threadIdx.x;   // global pair index
    if (t >= ps.cum[8]) return;
    int m = 0;
    #pragma unroll
    for (int i = 1; i < 8; i++) if (t >= ps.cum[i]) m = i;
    int p  = t - ps.cum[m];
    int K  = ps.K[m];
    int kh = K >> 1;
    int n  = p / kh;
    int kp = p - n*kh;
    int kstep = kp >> 3;
    int pp = kp & 7;
    int kq = pp & 3, khi = pp >> 2;
    int gid = n & 7, n8b = n >> 3;
    int sig = kq*8 + ((gid + 2*kq) & 7);
    int idx = ps.cum[m] + ((n8b*(K>>4) + kstep)*32 + sig)*2 + khi;
    const float* W = ps.W[m];
    int k = kp*2;
    unsigned hi, lo;
    split_bf16x2(W[(size_t)n*K + k], W[(size_t)n*K + k + 1], hi, lo);
    g_WH[idx] = hi;
    g_WL[idx] = lo;
}

// ---------------- tensor-core GEMM (3xBF16 m16n8k16, double-buffered,
// fragment-order smem; B loaded pre-split from g_WH/g_WL) ----------------
// C = act(A[M,K](lda) * W[N,K]^T + bias); M%128==0, K%16==0, N%8==0.
__global__ __launch_bounds__(256, 2)
void gemm_bf16_kernel(const float* __restrict__ A, int lda,
                      const unsigned* __restrict__ WH,
                      const unsigned* __restrict__ WL,
                      int nN8,
                      const float* __restrict__ bias,
                      float* __restrict__ C,
                      int M, int N, int K, int act) {
    __shared__ uint4 AH4[2][8][32];
    __shared__ uint4 AL4[2][8][32];
    __shared__ uint2 BH2[2][16][32];
    __shared__ uint2 BL2[2][16][32];

    int tid  = threadIdx.x;
    int lane = tid & 31;
    int wid  = tid >> 5;
    int wm = wid >> 2;
    int wn = wid & 3;
    int gid = lane >> 2;
    int kq  = lane & 3;
    int slot = kq*8 + ((gid + 2*kq) & 7);

    int m0 = blockIdx.y * 128;
    int n0 = blockIdx.x * 128;
    int nKt = K >> 4;

    // A producer coords
    int lr  = tid >> 1;
    int khi = tid & 1;
    int lcb = khi * 8;
    int am16b = lr >> 4;
    int pgid  = lr & 7;
    int ahalf = (lr >> 3) & 1;
    int regA  = ahalf + 2*khi;
    int s0 =      ((pgid    ) & 7);
    int s1 = 8  + ((pgid + 2) & 7);
    int s2 = 16 + ((pgid + 4) & 7);
    int s3 = 24 + ((pgid + 6) & 7);

    // B producer coords: 2 uint2 per thread per array
    int f0 = tid*2, f1 = f0+1;
    int nb0 = f0 >> 5, sg0 = f0 & 31;
    int nb1 = f1 >> 5, sg1 = f1 & 31;
    int bW = n0 >> 3;
    bool v0 = (bW + nb0) < nN8;
    bool v1 = (bW + nb1) < nN8;
    const uint2* WH2 = (const uint2*)WH;
    const uint2* WL2 = (const uint2*)WL;
    size_t wb0 = (size_t)(bW+nb0)*nKt*32 + sg0;
    size_t wb1 = (size_t)(bW+nb1)*nKt*32 + sg1;

    float acc[4][4][4];
    #pragma unroll
    for (int i=0;i<4;i++)
        #pragma unroll
        for (int j=0;j<4;j++)
            #pragma unroll
            for (int r=0;r<4;r++) acc[i][j][r]=0.f;

    const float* aptr = A + (size_t)(m0+lr)*lda + lcb;

    // prologue: stage 0
    float4 a4  = *(const float4*)aptr;
    float4 a4b = *(const float4*)(aptr + 4);
    uint2 bh0 = v0 ? WH2[wb0] : make_uint2(0u,0u);
    uint2 bh1 = v1 ? WH2[wb1] : make_uint2(0u,0u);
    uint2 bl0 = v0 ? WL2[wb0] : make_uint2(0u,0u);
    uint2 bl1 = v1 ? WL2[wb1] : make_uint2(0u,0u);
    {
        unsigned h, l;
        split_bf16x2(a4.x,  a4.y,  h, l);
        ((unsigned*)&AH4[0][am16b][s0])[regA]=h; ((unsigned*)&AL4[0][am16b][s0])[regA]=l;
        split_bf16x2(a4.z,  a4.w,  h, l);
        ((unsigned*)&AH4[0][am16b][s1])[regA]=h; ((unsigned*)&AL4[0][am16b][s1])[regA]=l;
        split_bf16x2(a4b.x, a4b.y, h, l);
        ((unsigned*)&AH4[0][am16b][s2])[regA]=h; ((unsigned*)&AL4[0][am16b][s2])[regA]=l;
        split_bf16x2(a4b.z, a4b.w, h, l);
        ((unsigned*)&AH4[0][am16b][s3])[regA]=h; ((unsigned*)&AL4[0][am16b][s3])[regA]=l;
        BH2[0][nb0][sg0]=bh0; BH2[0][nb1][sg1]=bh1;
        BL2[0][nb0][sg0]=bl0; BL2[0][nb1][sg1]=bl1;
    }
    __syncthreads();

    int nIter = K >> 4;
    for (int it = 0; it < nIter; it++) {
        int s = it & 1;
        bool more = (it + 1) < nIter;

        if (more) {
            int ko = (it+1) << 4;
            a4  = *(const float4*)(aptr + ko);
            a4b = *(const float4*)(aptr + ko + 4);
            size_t o = (size_t)(it+1)*32;
            bh0 = v0 ? WH2[wb0 + o] : make_uint2(0u,0u);
            bh1 = v1 ? WH2[wb1 + o] : make_uint2(0u,0u);
            bl0 = v0 ? WL2[wb0 + o] : make_uint2(0u,0u);
            bl1 = v1 ? WL2[wb1 + o] : make_uint2(0u,0u);
        }

        unsigned fah[4][4];
        #pragma unroll
        for (int mi=0; mi<4; mi++) {
            uint4 v = AH4[s][wm*4+mi][slot];
            fah[mi][0]=v.x; fah[mi][1]=v.y; fah[mi][2]=v.z; fah[mi][3]=v.w;
        }
        unsigned fb[4][2];
        #pragma unroll
        for (int ni=0; ni<4; ni++) {
            uint2 v = BH2[s][wn*4+ni][slot];
            fb[ni][0]=v.x; fb[ni][1]=v.y;
        }
        #pragma unroll
        for (int mi=0; mi<4; mi++)
            #pragma unroll
            for (int ni=0; ni<4; ni++)
                mma_bf16(acc[mi][ni], fah[mi], fb[ni]);
        {
            unsigned fal[4][4];
            #pragma unroll
            for (int mi=0; mi<4; mi++) {
                uint4 v = AL4[s][wm*4+mi][slot];
                fal[mi][0]=v.x; fal[mi][1]=v.y; fal[mi][2]=v.z; fal[mi][3]=v.w;
            }
            #pragma unroll
            for (int mi=0; mi<4; mi++)
                #pragma unroll
                for (int ni=0; ni<4; ni++)
                    mma_bf16(acc[mi][ni], fal[mi], fb[ni]);
        }
        #pragma unroll
        for (int ni=0; ni<4; ni++) {
            uint2 v = BL2[s][wn*4+ni][slot];
            fb[ni][0]=v.x; fb[ni][1]=v.y;
        }
        #pragma unroll
        for (int mi=0; mi<4; mi++)
            #pragma unroll
            for (int ni=0; ni<4; ni++)
                mma_bf16(acc[mi][ni], fah[mi], fb[ni]);

        if (more) {
            int d = s ^ 1;
            unsigned h, l;
            split_bf16x2(a4.x,  a4.y,  h, l);
            ((unsigned*)&AH4[d][am16b][s0])[regA]=h; ((unsigned*)&AL4[d][am16b][s0])[regA]=l;
            split_bf16x2(a4.z,  a4.w,  h, l);
            ((unsigned*)&AH4[d][am16b][s1])[regA]=h; ((unsigned*)&AL4[d][am16b][s1])[regA]=l;
            split_bf16x2(a4b.x, a4b.y, h, l);
            ((unsigned*)&AH4[d][am16b][s2])[regA]=h; ((unsigned*)&AL4[d][am16b][s2])[regA]=l;
            split_bf16x2(a4b.z, a4b.w, h, l);
            ((unsigned*)&AH4[d][am16b][s3])[regA]=h; ((unsigned*)&AL4[d][am16b][s3])[regA]=l;
            BH2[d][nb0][sg0]=bh0; BH2[d][nb1][sg1]=bh1;
            BL2[d][nb0][sg0]=bl0; BL2[d][nb1][sg1]=bl1;
        }
        __syncthreads();
    }

    #pragma unroll
    for (int mi=0; mi<4; mi++) {
        int r = m0 + wm*64 + mi*16 + gid;
        #pragma unroll
        for (int ni=0; ni<4; ni++) {
            int c = n0 + wn*32 + ni*8 + kq*2;
            if (c < N) {
                float v0e = acc[mi][ni][0], v1e = acc[mi][ni][1];
                float v2e = acc[mi][ni][2], v3e = acc[mi][ni][3];
                if (bias) {
                    float b0 = bias[c], b1 = bias[c+1];
                    v0e += b0; v1e += b1; v2e += b0; v3e += b1;
                }
                if (act == 1) {
                    v0e=fmaxf(v0e,0.f); v1e=fmaxf(v1e,0.f); v2e=fmaxf(v2e,0.f); v3e=fmaxf(v3e,0.f);
                } else if (act == 2) {
                    v0e = fsoftplus(v0e);
                    v1e = fsoftplus(v1e);
                    v2e = fsoftplus(v2e);
                    v3e = fsoftplus(v3e);
                }
                *(float2*)(C + (size_t)r*N + c)       = make_float2(v0e, v1e);
                *(float2*)(C + (size_t)(r+8)*N + c)   = make_float2(v2e, v3e);
            }
        }
    }
}

// ---------------- causal depthwise conv (DC=4) + SiLU (FMA-pipe) ----------------
__global__ void conv_silu_kernel(const float* __restrict__ conv_w,
                                 const float* __restrict__ conv_b) {
    int i = blockIdx.x * blockDim.x + threadIdx.x;
    int row = i >> 9;
    int d   = i & (DI-1);
    int b   = row >> 9;
    int l   = row & (LL-1);
    float acc = conv_b[d];
    #pragma unroll
    for (int k=0;k<DC;k++) {
        int ll = l - (DC-1) + k;
        if (ll >= 0)
            acc = fmaf(g_xz[(size_t)((b<<9)+ll)*(2*DI) + d], conv_w[d*DC + k], acc);
    }
    g_uconv[i] = fsilu(acc);
}

// ---------------- selective scan v2 (FMA-pipe transcendentals) ----------------
#define TCH 16
__global__ __launch_bounds__(128)
void scan2_kernel(const float* __restrict__ A_log,
                  const float* __restrict__ Dp) {
    __shared__ float sBC[TCH][64];
    int b = blockIdx.x >> 2;
    int q = blockIdx.x & 3;
    int d = q*128 + threadIdx.x;
    int brow = b << 9;

    float h[32];
    #pragma unroll
    for (int n=0;n<32;n++) h[n]=0.f;
    float dpv = Dp[d];

    bool fast = true;
    #pragma unroll
    for (int n=0;n<32;n++) {
        float a = -__expf(A_log[d*NN + n]);
        if (fabsf(a + (float)(n+1)) > 1e-3f*(float)(n+1)) fast = false;
    }

    for (int t0=0; t0<LL; t0+=TCH) {
        __syncthreads();
        #pragma unroll
        for (int it=0; it<2; it++) {
            int p  = it*128 + threadIdx.x;
            int t  = p >> 4;
            int j  = (p & 15) * 4;
            *(float4*)&sBC[t][j] =
                *(const float4*)&g_xdbl[(size_t)(brow+t0+t)*80 + DTR + j];
        }
        __syncthreads();

        if (fast) {
            #pragma unroll 4
            for (int tt=0; tt<TCH; tt++) {
                int row = brow + t0 + tt;
                float dtv = g_dt   [(size_t)row*DI + d];
                float uv  = g_uconv[(size_t)row*DI + d];
                float p  = fexp(-dtv);
                float du = dtv * uv;
                float w  = 1.f;
                float y0=0.f,y1=0.f,y2=0.f,y3=0.f;
                #pragma unroll
                for (int n=0;n<32;n+=4) {
                    w *= p; h[n  ]=fmaf(w,h[n  ],du*sBC[tt][n  ]); y0=fmaf(h[n  ],sBC[tt][32+n  ],y0);
                    w *= p; h[n+1]=fmaf(w,h[n+1],du*sBC[tt][n+1]); y1=fmaf(h[n+1],sBC[tt][33+n  ],y1);
                    w *= p; h[n+2]=fmaf(w,h[n+2],du*sBC[tt][n+2]); y2=fmaf(h[n+2],sBC[tt][34+n  ],y2);
                    w *= p; h[n+3]=fmaf(w,h[n+3],du*sBC[tt][n+3]); y3=fmaf(h[n+3],sBC[tt][35+n  ],y3);
                }
                float y = (y0+y1)+(y2+y3);
                float z  = g_xz[(size_t)row*(2*DI) + DI + d];
                g_ymam[(size_t)row*DI + d] = (y + uv*dpv) * fsilu(z);
            }
        } else {
            for (int tt=0; tt<TCH; tt++) {
                int row = brow + t0 + tt;
                float dtv = g_dt   [(size_t)row*DI + d];
                float uv  = g_uconv[(size_t)row*DI + d];
                float du = dtv * uv;
                float y = 0.f;
                #pragma unroll
                for (int n=0;n<32;n++) {
                    float a = -__expf(A_log[d*NN + n]);
                    float e = fexp(dtv * a);
                    h[n] = fmaf(e, h[n], du*sBC[tt][n]);
                    y = fmaf(h[n], sBC[tt][32+n], y);
                }
                float z  = g_xz[(size_t)row*(2*DI) + DI + d];
                g_ymam[(size_t)row*DI + d] = (y + uv*dpv) * fsilu(z);
            }
        }
    }
}

// ---------------- attention: FA2-style bf16 mma ----------------
__global__ __launch_bounds__(256)
void attn_mma_kernel() {
    __shared__ uint2 KH[2][4][32], KL[2][4][32];
    __shared__ uint2 VH[2][4][32], VL[2][4][32];

    int bh = blockIdx.x >> 1;
    int qh = blockIdx.x & 1;
    int b  = bh >> 3, h = bh & 7;
    int brow = b << 9;
    int tid = threadIdx.x;
    int w = tid >> 5, lane = tid & 31;
    int gid = lane >> 2, kq = lane & 3;
    int slot = kq*8 + ((gid + 2*kq) & 7);
    const float scale = 0.17677669529663687f;

    int qb = qh*256 + w*32;
    unsigned qa_h[2][2][4], qa_l[2][2][4];
    #pragma unroll
    for (int mi=0; mi<2; mi++) {
        int r0 = brow + qb + mi*16 + gid;
        const float* q0 = g_qkv + (size_t)r0*(3*EE) + h*32;
        const float* q1 = q0 + (size_t)8*(3*EE);
        #pragma unroll
        for (int ks=0; ks<2; ks++) {
            int dA = 16*ks + 2*kq;
            float2 v0 = *(const float2*)(q0 + dA);
            float2 v1 = *(const float2*)(q1 + dA);
            float2 v2 = *(const float2*)(q0 + dA + 8);
            float2 v3 = *(const float2*)(q1 + dA + 8);
            split_bf16x2(v0.x*scale, v0.y*scale, qa_h[mi][ks][0], qa_l[mi][ks][0]);
            split_bf16x2(v1.x*scale, v1.y*scale, qa_h[mi][ks][1], qa_l[mi][ks][1]);
            split_bf16x2(v2.x*scale, v2.y*scale, qa_h[mi][ks][2], qa_l[mi][ks][2]);
            split_bf16x2(v3.x*scale, v3.y*scale, qa_h[mi][ks][3], qa_l[mi][ks][3]);
        }
    }

    float o[2][4][4];
    #pragma unroll
    for (int mi=0;mi<2;mi++)
        #pragma unroll
        for (int vb=0;vb<4;vb++)
            #pragma unroll
            for (int c=0;c<4;c++) o[mi][vb][c]=0.f;
    float mrun[2][2] = {{-1e30f,-1e30f},{-1e30f,-1e30f}};
    float lrun[2][2] = {{0.f,0.f},{0.f,0.f}};

    int pkn  = tid >> 3;
    int pkd0 = (tid & 7) * 4;
    int pkks = pkd0 >> 4;
    int pkp0 = (pkd0 & 15) >> 1;
    int pkkq0 = pkp0 & 3, pkkhi = pkp0 >> 2;
    int pkbn = pkn >> 3, pkg = pkn & 7;
    int pksA = pkkq0*8 + ((pkg + 2*pkkq0) & 7);
    int pksB = (pkkq0+1)*8 + ((pkg + 2*(pkkq0+1)) & 7);
    int pvp  = tid >> 4;
    int pvd0 = (tid & 15) * 2;
    int pvks = pvp >> 3;
    int pvq  = (pvp & 7) & 3, pvkhi = (pvp & 7) >> 2;
    int pvbnA = pvd0 >> 3,      pvsA = pvq*8 + (((pvd0 & 7) + 2*pvq) & 7);
    int pvbnB = (pvd0+1) >> 3,  pvsB = pvq*8 + ((((pvd0+1) & 7) + 2*pvq) & 7);

    for (int kt = 0; kt < 16; kt++) {
        __syncthreads();
        {
            const float* kp = g_qkv + (size_t)(brow + kt*32 + pkn)*(3*EE) + EE + h*32 + pkd0;
            float4 kv = *(const float4*)kp;
            unsigned hi, lo;
            split_bf16x2(kv.x, kv.y, hi, lo);
            ((unsigned*)&KH[pkks][pkbn][pksA])[pkkhi]=hi; ((unsigned*)&KL[pkks][pkbn][pksA])[pkkhi]=lo;
            split_bf16x2(kv.z, kv.w, hi, lo);
            ((unsigned*)&KH[pkks][pkbn][pksB])[pkkhi]=hi; ((unsigned*)&KL[pkks][pkbn][pksB])[pkkhi]=lo;
        }
        {
            const float* v0p = g_qkv + (size_t)(brow + kt*32 + 2*pvp)*(3*EE) + 2*EE + h*32 + pvd0;
            const float* v1p = v0p + 3*EE;
            float2 va = *(const float2*)v0p;
            float2 vb = *(const float2*)v1p;
            unsigned hi, lo;
            split_bf16x2(va.x, vb.x, hi, lo);
            ((unsigned*)&VH[pvks][pvbnA][pvsA])[pvkhi]=hi; ((unsigned*)&VL[pvks][pvbnA][pvsA])[pvkhi]=lo;
            split_bf16x2(va.y, vb.y, hi, lo);
            ((unsigned*)&VH[pvks][pvbnB][pvsB])[pvkhi]=hi; ((unsigned*)&VL[pvks][pvbnB][pvsB])[pvkhi]=lo;
        }
        __syncthreads();

        float sa[2][4][4];
        #pragma unroll
        for (int mi=0;mi<2;mi++)
            #pragma unroll
            for (int bn=0;bn<4;bn++)
                #pragma unroll
                for (int c=0;c<4;c++) sa[mi][bn][c]=0.f;
        #pragma unroll
        for (int bn=0; bn<4; bn++) {
            #pragma unroll
            for (int ks=0; ks<2; ks++) {
                uint2 kh2 = KH[ks][bn][slot];
                unsigned kh[2] = {kh2.x, kh2.y};
                uint2 kl2 = KL[ks][bn][slot];
                unsigned kl[2] = {kl2.x, kl2.y};
                #pragma unroll
                for (int mi=0; mi<2; mi++) {
                    mma_bf16(sa[mi][bn], qa_h[mi][ks], kh);
                    mma_bf16(sa[mi][bn], qa_l[mi][ks], kh);
                    mma_bf16(sa[mi][bn], qa_h[mi][ks], kl);
                }
            }
        }

        #pragma unroll
        for (int mi=0; mi<2; mi++) {
            #pragma unroll
            for (int rr=0; rr<2; rr++) {
                int c0 = rr*2;
                float mx = -1e30f;
                #pragma unroll
                for (int bn=0; bn<4; bn++) {
                    mx = fmaxf(mx, sa[mi][bn][c0]);
                    mx = fmaxf(mx, sa[mi][bn][c0+1]);
                }
                mx = fmaxf(mx, __shfl_xor_sync(0xffffffffu, mx, 1));
                mx = fmaxf(mx, __shfl_xor_sync(0xffffffffu, mx, 2));
                float mnew = fmaxf(mrun[mi][rr], mx);
                float corr = fexp(mrun[mi][rr] - mnew);
                mrun[mi][rr] = mnew;
                float psum = 0.f;
                #pragma unroll
                for (int bn=0; bn<4; bn++) {
                    float p0 = fexp(sa[mi][bn][c0]   - mnew);
                    float p1 = fexp(sa[mi][bn][c0+1] - mnew);
                    sa[mi][bn][c0]   = p0;
                    sa[mi][bn][c0+1] = p1;
                    psum += p0 + p1;
                }
                psum += __shfl_xor_sync(0xffffffffu, psum, 1);
                psum += __shfl_xor_sync(0xffffffffu, psum, 2);
                lrun[mi][rr] = lrun[mi][rr]*corr + psum;
                #pragma unroll
                for (int vb=0; vb<4; vb++) {
                    o[mi][vb][c0]   *= corr;
                    o[mi][vb][c0+1] *= corr;
                }
            }
        }

        #pragma unroll
        for (int mi=0; mi<2; mi++) {
            #pragma unroll
            for (int j=0; j<2; j++) {
                unsigned pa_h[4], pa_l[4];
                split_bf16x2(sa[mi][2*j  ][0], sa[mi][2*j  ][1], pa_h[0], pa_l[0]);
                split_bf16x2(sa[mi][2*j  ][2], sa[mi][2*j  ][3], pa_h[1], pa_l[1]);
                split_bf16x2(sa[mi][2*j+1][0], sa[mi][2*j+1][1], pa_h[2], pa_l[2]);
                split_bf16x2(sa[mi][2*j+1][2], sa[mi][2*j+1][3], pa_h[3], pa_l[3]);
                #pragma unroll
                for (int vb=0; vb<4; vb++) {
                    uint2 vh2 = VH[j][vb][slot];
                    unsigned vh[2] = {vh2.x, vh2.y};
                    mma_bf16(o[mi][vb], pa_h, vh);
                    mma_bf16(o[mi][vb], pa_l, vh);
                    uint2 vl2 = VL[j][vb][slot];
                    unsigned vl[2] = {vl2.x, vl2.y};
                    mma_bf16(o[mi][vb], pa_h, vl);
                }
            }
        }
    }

    #pragma unroll
    for (int mi=0; mi<2; mi++) {
        float inv0 = 1.f / lrun[mi][0];
        float inv1 = 1.f / lrun[mi][1];
        int r0 = brow + qb + mi*16 + gid;
        float* c0p = g_ctx + (size_t)r0*EE + h*32;
        float* c1p = c0p + (size_t)8*EE;
        #pragma unroll
        for (int vb=0; vb<4; vb++) {
            int cc = vb*8 + kq*2;
            *(float2*)(c0p + cc) = make_float2(o[mi][vb][0]*inv0, o[mi][vb][1]*inv0);
            *(float2*)(c1p + cc) = make_float2(o[mi][vb][2]*inv1, o[mi][vb][3]*inv1);
        }
    }
}

// ---------------- fused: add + LN(ln1) + gated combine -> g_comb ----------------
__global__ void add_ln_combine_kernel(const float* __restrict__ x, const float* __restrict__ res,
                                      const float* __restrict__ g, const float* __restrict__ bta) {
    int row  = blockIdx.x * (blockDim.x >> 5) + (threadIdx.x >> 5);
    int lane = threadIdx.x & 31;
    const float4* xp = (const float4*)(x   + (size_t)row*EE);
    const float4* rp = (const float4*)(res + (size_t)row*EE);
    float v[8];
    float4 a0 = xp[lane],     b0 = rp[lane];
    float4 a1 = xp[lane+32],  b1 = rp[lane+32];
    v[0]=a0.x+b0.x; v[1]=a0.y+b0.y; v[2]=a0.z+b0.z; v[3]=a0.w+b0.w;
    v[4]=a1.x+b1.x; v[5]=a1.y+b1.y; v[6]=a1.z+b1.z; v[7]=a1.w+b1.w;
    float s=0.f, s2=0.f;
    #pragma unroll
    for (int i=0;i<8;i++){ s += v[i]; s2 = fmaf(v[i], v[i], s2); }
    #pragma unroll
    for (int off=16; off; off>>=1) {
        s  += __shfl_xor_sync(0xffffffffu, s,  off);
        s2 += __shfl_xor_sync(0xffffffffu, s2, off);
    }
    float mean = s * (1.f/EE);
    float var  = s2 * (1.f/EE) - mean*mean;
    float rstd = rsqrtf(var + 1e-6f);
    const float4* gp = (const float4*)g;
    const float4* bp = (const float4*)bta;
    float4 g0=gp[lane], g1=gp[lane+32], c0=bp[lane], c1=bp[lane+32];
    const float4* mp = (const float4*)(g_mamba + (size_t)row*EE);
    float4 m0 = mp[lane], m1 = mp[lane+32];
    float w = g_gate[row >> 9];
    float iw = 1.f - w;
    float4* op = (float4*)(g_comb + (size_t)row*EE);
    float4 o0, o1;
    o0.x = w*m0.x + iw*((v[0]-mean)*rstd*g0.x+c0.x);
    o0.y = w*m0.y + iw*((v[1]-mean)*rstd*g0.y+c0.y);
    o0.z = w*m0.z + iw*((v[2]-mean)*rstd*g0.z+c0.z);
    o0.w = w*m0.w + iw*((v[3]-mean)*rstd*g0.w+c0.w);
    o1.x = w*m1.x + iw*((v[4]-mean)*rstd*g1.x+c1.x);
    o1.y = w*m1.y + iw*((v[5]-mean)*rstd*g1.y+c1.y);
    o1.z = w*m1.z + iw*((v[6]-mean)*rstd*g1.z+c1.z);
    o1.w = w*m1.w + iw*((v[7]-mean)*rstd*g1.w+c1.w);
    op[lane]    = o0;
    op[lane+32] = o1;
}

// ---------------- fused: add + LN(ln2) + pos/neg logits -> out ----------------
__global__ void add_ln_logits_kernel(const float* __restrict__ x, const float* __restrict__ res,
                                     const float* __restrict__ g, const float* __restrict__ bta,
                                     const int* __restrict__ pos, const int* __restrict__ neg,
                                     const float* __restrict__ item_emb, float* __restrict__ out) {
    int row  = blockIdx.x * (blockDim.x >> 5) + (threadIdx.x >> 5);
    int lane = threadIdx.x & 31;
    const float4* xp = (const float4*)(x   + (size_t)row*EE);
    const float4* rp = (const float4*)(res + (size_t)row*EE);
    float v[8];
    float4 a0 = xp[lane],     b0 = rp[lane];
    float4 a1 = xp[lane+32],  b1 = rp[lane+32];
    v[0]=a0.x+b0.x; v[1]=a0.y+b0.y; v[2]=a0.z+b0.z; v[3]=a0.w+b0.w;
    v[4]=a1.x+b1.x; v[5]=a1.y+b1.y; v[6]=a1.z+b1.z; v[7]=a1.w+b1.w;
    float s=0.f, s2=0.f;
    #pragma unroll
    for (int i=0;i<8;i++){ s += v[i]; s2 = fmaf(v[i], v[i], s2); }
    #pragma unroll
    for (int off=16; off; off>>=1) {
        s  += __shfl_xor_sync(0xffffffffu, s,  off);
        s2 += __shfl_xor_sync(0xffffffffu, s2, off);
    }
    float mean = s * (1.f/EE);
    float var  = s2 * (1.f/EE) - mean*mean;
    float rstd = rsqrtf(var + 1e-6f);
    const float4* gp = (const float4*)g;
    const float4* bp = (const float4*)bta;
    float4 g0=gp[lane], g1=gp[lane+32], c0=bp[lane], c1=bp[lane+32];
    float f[8];
    f[0]=(v[0]-mean)*rstd*g0.x+c0.x; f[1]=(v[1]-mean)*rstd*g0.y+c0.y;
    f[2]=(v[2]-mean)*rstd*g0.z+c0.z; f[3]=(v[3]-mean)*rstd*g0.w+c0.w;
    f[4]=(v[4]-mean)*rstd*g1.x+c1.x; f[5]=(v[5]-mean)*rstd*g1.y+c1.y;
    f[6]=(v[6]-mean)*rstd*g1.z+c1.z; f[7]=(v[7]-mean)*rstd*g1.w+c1.w;
    int pi = __ldg(&pos[row]), ni = __ldg(&neg[row]);
    const float4* pe = (const float4*)(item_emb + (size_t)pi*EE);
    const float4* ne = (const float4*)(item_emb + (size_t)ni*EE);
    float4 p0 = pe[lane], p1 = pe[lane+32];
    float4 n0 = ne[lane], n1 = ne[lane+32];
    float dp = f[0]*p0.x+f[1]*p0.y+f[2]*p0.z+f[3]*p0.w
             + f[4]*p1.x+f[5]*p1.y+f[6]*p1.z+f[7]*p1.w;
    float dn = f[0]*n0.x+f[1]*n0.y+f[2]*n0.z+f[3]*n0.w
             + f[4]*n1.x+f[5]*n1.y+f[6]*n1.z+f[7]*n1.w;
    #pragma unroll
    for (int off=16; off; off>>=1) {
        dp += __shfl_xor_sync(0xffffffffu, dp, off);
        dn += __shfl_xor_sync(0xffffffffu, dn, off);
    }
    if (lane == 0) {
        out[row]         = dp;
        out[MROWS + row] = dn;
    }
}

// ---------------- gate ----------------
__global__ void gate_kernel(const float* __restrict__ mw_w, const float* __restrict__ mw_b) {
    int b = blockIdx.x;
    int e = threadIdx.x;
    float s = 0.f;
    for (int l=0;l<LL;l++) s += g_seqs[(size_t)((b<<9)+l)*EE + e];
    s = (s * (1.f/LL)) * mw_w[e];
    __shared__ float red[256];
    red[e] = s; __syncthreads();
    for (int st=128; st; st>>=1) { if (e < st) red[e] += red[e+st]; __syncthreads(); }
    if (e == 0) g_gate[b] = 1.f / (1.f + __expf(-(red[0] + mw_b[0])));
}

// ---------------- host ----------------
static float* symaddr(const void* sym) {
    void* p = nullptr;
    cudaGetSymbolAddress(&p, sym);
    return (float*)p;
}

// matrix order: in_proj, x_proj, dt_proj, out_proj, attn_in, attn_out, ff1, ff2
static const int WBASE[9] = {0, 131072, 151552, 155648, 221184, 319488, 352256, 483328, 614400};

static void gemm(const float* A, int lda, const unsigned* WH, const unsigned* WL,
                 const float* bias, float* C, int M, int N, int K, int act) {
    dim3 grid((N + 127) / 128, M / 128);
    gemm_bf16_kernel<<<grid, 256>>>(A, lda, WH, WL, N >> 3, bias, C, M, N, K, act);
}

extern "C" void kernel_launch(void* const* d_in, const int* in_sizes, int n_in,
                              void* d_out, int out_size) {
    const int*   log_seqs  = (const int*)  d_in[1];
    const int*   pos_seqs  = (const int*)  d_in[2];
    const int*   neg_seqs  = (const int*)  d_in[3];
    const float* item_emb  = (const float*)d_in[4];
    const float* pos_emb   = (const float*)d_in[5];
    const float* in_proj_w = (const float*)d_in[6];
    const float* conv_w    = (const float*)d_in[7];
    const float* conv_b    = (const float*)d_in[8];
    const float* x_proj_w  = (const float*)d_in[9];
    const float* dt_proj_w = (const float*)d_in[10];
    const float* dt_proj_b = (const float*)d_in[11];
    const float* A_log     = (const float*)d_in[12];
    const float* Dp        = (const float*)d_in[13];
    const float* out_proj_w= (const float*)d_in[14];
    const float* attn_in_w = (const float*)d_in[15];
    const float* attn_in_b = (const float*)d_in[16];
    const float* attn_out_w= (const float*)d_in[17];
    const float* attn_out_b= (const float*)d_in[18];
    const float* ln1_g     = (const float*)d_in[19];
    const float* ln1_b     = (const float*)d_in[20];
    const float* mw_w      = (const float*)d_in[21];
    const float* mw_b      = (const float*)d_in[22];
    const float* ff_w1     = (const float*)d_in[23];
    const float* ff_b1     = (const float*)d_in[24];
    const float* ff_w2     = (const float*)d_in[25];
    const float* ff_b2     = (const float*)d_in[26];
    const float* ln2_g     = (const float*)d_in[27];
    const float* ln2_b     = (const float*)d_in[28];
    float* out = (float*)d_out;

    float* p_seqs   = symaddr(g_seqs);
    float* p_xz     = symaddr(g_xz);
    float* p_uconv  = symaddr(g_uconv);
    float* p_xdbl   = symaddr(g_xdbl);
    float* p_dt     = symaddr(g_dt);
    float* p_ymam   = symaddr(g_ymam);
    float* p_mamba  = symaddr(g_mamba);
    float* p_qkv    = symaddr(g_qkv);
    float* p_ctx    = symaddr(g_ctx);
    float* p_attno  = symaddr(g_attno);
    float* p_comb   = symaddr(g_comb);
    float* p_ffh    = symaddr(g_ffh);
    float* p_ff     = symaddr(g_ff);
    unsigned* p_WH  = (unsigned*)symaddr(g_WH);
    unsigned* p_WL  = (unsigned*)symaddr(g_WL);

    // 0. pre-split all weights into fragment-order bf16 hi/lo
    PSDesc ps;
    ps.W[0]=in_proj_w;  ps.K[0]=256;
    ps.W[1]=x_proj_w;   ps.K[1]=512;
    ps.W[2]=dt_proj_w;  ps.K[2]=16;
    ps.W[3]=out_proj_w; ps.K[3]=512;
    ps.W[4]=attn_in_w;  ps.K[4]=256;
    ps.W[5]=attn_out_w; ps.K[5]=256;
    ps.W[6]=ff_w1;      ps.K[6]=256;
    ps.W[7]=ff_w2;      ps.K[7]=1024;
    for (int i=0;i<9;i++) ps.cum[i] = WBASE[i];
    presplit_kernel<<<(WTOT + 255)/256, 256>>>(ps);

    // 1. embedding + positional; gate
    embed_kernel<<<(MROWS*EE)/256, 256>>>(log_seqs, item_emb, pos_emb);
    gate_kernel<<<BB, 256>>>(mw_w, mw_b);

    // 2. Mamba branch
    gemm(p_seqs, EE, p_WH+WBASE[0], p_WL+WBASE[0], nullptr, p_xz, MROWS, 2*DI, EE, 0);
    conv_silu_kernel<<<(MROWS*DI)/256, 256>>>(conv_w, conv_b);
    gemm(p_uconv, DI, p_WH+WBASE[1], p_WL+WBASE[1], nullptr, p_xdbl, MROWS, DTR+2*NN, DI, 0);
    gemm(p_xdbl, 80, p_WH+WBASE[2], p_WL+WBASE[2], dt_proj_b, p_dt, MROWS, DI, DTR, 2);  // softplus
    scan2_kernel<<<BB*4, 128>>>(A_log, Dp);
    gemm(p_ymam, DI, p_WH+WBASE[3], p_WL+WBASE[3], nullptr, p_mamba, MROWS, EE, DI, 0);

    // 3. attention branch (tensor-core FA2)
    gemm(p_seqs, EE, p_WH+WBASE[4], p_WL+WBASE[4], attn_in_b, p_qkv, MROWS, 3*EE, EE, 0);
    attn_mma_kernel<<<BB*HH*2, 256>>>();
    gemm(p_ctx, EE, p_WH+WBASE[5], p_WL+WBASE[5], attn_out_b, p_attno, MROWS, EE, EE, 0);

    // 4. fused add+LN1+combine
    add_ln_combine_kernel<<<MROWS/8, 256>>>(p_attno, p_seqs, ln1_g, ln1_b);

    // 5. FFN + fused add+LN2+logits
    gemm(p_comb, EE, p_WH+WBASE[6], p_WL+WBASE[6], ff_b1, p_ffh, MROWS, 4*EE, EE, 1);
    gemm(p_ffh, 4*EE, p_WH+WBASE[7], p_WL+WBASE[7], ff_b2, p_ff, MROWS, EE, 4*EE, 0);
    add_ln_logits_kernel<<<MROWS/8, 256>>>(p_ff, p_comb, ln2_g, ln2_b,
                                           pos_seqs, neg_seqs, item_emb, out);
}